// round 1
// baseline (speedup 1.0000x reference)
#include <cuda_runtime.h>
#include <math.h>

#define B_TOT 2048
#define D     768
#define DH    384
#define NPOS  20
#define OUTSZ (2048*12*20*64)   // per Q/K/V output: 31,457,280 floats

// ---------------- scratch (static device globals; no allocation) ----------------
__device__ float g_t1[B_TOT * NPOS * DH];   // gelu(1x1 conv) activations, [m=b*20+p][384]
__device__ float g_w2t[DH * 9 * D];         // w2 transposed to [(i*9+tap)*768 + o]
__device__ float g_filt[B_TOT * 4 * D];     // filtered rows, [(b*4+y)*768 + o]

typedef unsigned long long u64;

// ---------------- f32x2 helpers (packed fp32 pair FMA, sm_100+) ----------------
__device__ __forceinline__ u64 splat2(float v) {
    u64 r; unsigned u = __float_as_uint(v);
    asm("mov.b64 %0, {%1, %1};" : "=l"(r) : "r"(u));
    return r;
}
__device__ __forceinline__ void fma2(u64& a, u64 x, u64 y) {
    asm("fma.rn.f32x2 %0, %1, %2, %0;" : "+l"(a) : "l"(x), "l"(y));
}
__device__ __forceinline__ float2 unpack2(u64 v) {
    unsigned lo, hi;
    asm("mov.b64 {%0, %1}, %2;" : "=r"(lo), "=r"(hi) : "l"(v));
    return make_float2(__uint_as_float(lo), __uint_as_float(hi));
}
__device__ __forceinline__ float gelu_f(float v) {
    return 0.5f * v * (1.0f + erff(v * 0.7071067811865476f));
}

// ---------------- K0: transpose w2 (OIHW -> [i][tap][o]) ----------------
__global__ void k0_transpose(const float* __restrict__ w2) {
    int idx = blockIdx.x * 256 + threadIdx.x;
    if (idx >= DH * 9 * D) return;
    int o = idx % D;
    int r = idx / D;          // i*9 + tap
    int t = r % 9, i = r / 9;
    g_w2t[idx] = w2[(o * DH + i) * 9 + t];
}

// ---------------- K1: t1 = gelu(X @ W1^T), M=40960 N=384 K=768 ----------------
__global__ __launch_bounds__(256, 2) void k1_gemm(const float* __restrict__ X,
                                                  const float* __restrict__ W1) {
    __shared__ __align__(16) float As[16][128];
    __shared__ __align__(16) float Bs[16][128];
    const int m0 = blockIdx.x * 128;
    const int n0 = blockIdx.y * 128;
    const int tid = threadIdx.x;
    const int f0 = tid * 2, f1 = f0 + 1;
    const int ar0 = f0 >> 2, ak0 = (f0 & 3) << 2;
    const int ar1 = f1 >> 2, ak1 = (f1 & 3) << 2;
    const int mg0 = m0 + ar0, mg1 = m0 + ar1;
    // x row for m: token (1 + m%20) of batch m/20 -> offset (m + m/20 + 1)*768
    const float* Arow0 = X + (size_t)(mg0 + mg0 / 20 + 1) * 768 + ak0;
    const float* Arow1 = X + (size_t)(mg1 + mg1 / 20 + 1) * 768 + ak1;
    const float* Brow0 = W1 + (size_t)(n0 + ar0) * 768 + ak0;
    const float* Brow1 = W1 + (size_t)(n0 + ar1) * 768 + ak1;
    const int tx = tid & 15, ty = tid >> 4;

    u64 acc[8][4];
#pragma unroll
    for (int i = 0; i < 8; i++)
#pragma unroll
        for (int j = 0; j < 4; j++) acc[i][j] = 0ull;

    for (int k0i = 0; k0i < 768; k0i += 16) {
        float4 a0 = *(const float4*)(Arow0 + k0i);
        float4 a1 = *(const float4*)(Arow1 + k0i);
        float4 b0 = *(const float4*)(Brow0 + k0i);
        float4 b1 = *(const float4*)(Brow1 + k0i);
        __syncthreads();
        As[ak0 + 0][ar0] = a0.x; As[ak0 + 1][ar0] = a0.y; As[ak0 + 2][ar0] = a0.z; As[ak0 + 3][ar0] = a0.w;
        As[ak1 + 0][ar1] = a1.x; As[ak1 + 1][ar1] = a1.y; As[ak1 + 2][ar1] = a1.z; As[ak1 + 3][ar1] = a1.w;
        Bs[ak0 + 0][ar0] = b0.x; Bs[ak0 + 1][ar0] = b0.y; Bs[ak0 + 2][ar0] = b0.z; Bs[ak0 + 3][ar0] = b0.w;
        Bs[ak1 + 0][ar1] = b1.x; Bs[ak1 + 1][ar1] = b1.y; Bs[ak1 + 2][ar1] = b1.z; Bs[ak1 + 3][ar1] = b1.w;
        __syncthreads();
#pragma unroll
        for (int kk = 0; kk < 16; kk++) {
            float4 av0 = *(const float4*)&As[kk][ty * 8];
            float4 av1 = *(const float4*)&As[kk][ty * 8 + 4];
            ulonglong2 bb0 = *(const ulonglong2*)&Bs[kk][tx * 8];
            ulonglong2 bb1 = *(const ulonglong2*)&Bs[kk][tx * 8 + 4];
            u64 bp0 = bb0.x, bp1 = bb0.y, bp2 = bb1.x, bp3 = bb1.y;
            float am[8] = {av0.x, av0.y, av0.z, av0.w, av1.x, av1.y, av1.z, av1.w};
#pragma unroll
            for (int im = 0; im < 8; im++) {
                u64 s = splat2(am[im]);
                fma2(acc[im][0], s, bp0);
                fma2(acc[im][1], s, bp1);
                fma2(acc[im][2], s, bp2);
                fma2(acc[im][3], s, bp3);
            }
        }
    }
#pragma unroll
    for (int im = 0; im < 8; im++) {
        int m = m0 + ty * 8 + im;
        float vals[8];
#pragma unroll
        for (int j = 0; j < 4; j++) {
            float2 v = unpack2(acc[im][j]);
            vals[2 * j] = gelu_f(v.x);
            vals[2 * j + 1] = gelu_f(v.y);
        }
        float* dst = g_t1 + (size_t)m * 384 + n0 + tx * 8;
        *(float4*)dst = make_float4(vals[0], vals[1], vals[2], vals[3]);
        *(float4*)(dst + 4) = make_float4(vals[4], vals[5], vals[6], vals[7]);
    }
}

// ---------------- K2: conv3x3 + gelu + analytic FFT low-pass filter ----------------
// 2 batches per CTA (t1 tiles in smem), 256 threads = 64 o-pair lanes x {2 batches} x {2 o-halves}
__global__ __launch_bounds__(256, 1) void k2_conv() {
    extern __shared__ float s_t1[];   // [2][DH][NPOS]
    const int tid = threadIdx.x;
    const int bg0 = blockIdx.x * 2;
    for (int idx = tid; idx < 2 * NPOS * DH; idx += 256) {
        int b = idx / (NPOS * DH);
        int rem = idx - b * (NPOS * DH);
        int p = rem / DH;
        int i = rem - p * DH;
        s_t1[(b * DH + i) * NPOS + p] = g_t1[((size_t)(bg0 + b) * NPOS + p) * DH + i];
    }
    __syncthreads();
    const int lane = tid & 63;
    const int grp = tid >> 6;      // 0..3
    const int bi = grp & 1;
    const int oh = grp >> 1;       // which half of the 768 output channels
    const float* sb = s_t1 + bi * DH * NPOS;
    const int b = bg0 + bi;

    for (int ot = oh * 3; ot < oh * 3 + 3; ++ot) {
        const int o = ot * 128 + lane * 2;
        u64 acc[20];
#pragma unroll
        for (int p = 0; p < 20; p++) acc[p] = 0ull;
        const u64* wbase = (const u64*)(g_w2t + o);
        for (int i = 0; i < DH; i++) {
            const float* tr = sb + i * NPOS;
            float4 q0 = *(const float4*)tr;
            float4 q1 = *(const float4*)(tr + 4);
            float4 q2 = *(const float4*)(tr + 8);
            float4 q3 = *(const float4*)(tr + 12);
            float4 q4 = *(const float4*)(tr + 16);
            u64 tv[20];
            tv[0] = splat2(q0.x);  tv[1] = splat2(q0.y);  tv[2] = splat2(q0.z);  tv[3] = splat2(q0.w);
            tv[4] = splat2(q1.x);  tv[5] = splat2(q1.y);  tv[6] = splat2(q1.z);  tv[7] = splat2(q1.w);
            tv[8] = splat2(q2.x);  tv[9] = splat2(q2.y);  tv[10] = splat2(q2.z); tv[11] = splat2(q2.w);
            tv[12] = splat2(q3.x); tv[13] = splat2(q3.y); tv[14] = splat2(q3.z); tv[15] = splat2(q3.w);
            tv[16] = splat2(q4.x); tv[17] = splat2(q4.y); tv[18] = splat2(q4.z); tv[19] = splat2(q4.w);
            const u64* wr = wbase + (size_t)i * 9 * 384;  // (i*9+t)*768 floats
            u64 w[9];
#pragma unroll
            for (int t = 0; t < 9; t++) w[t] = wr[(size_t)t * 384];
#pragma unroll
            for (int y = 0; y < 4; y++)
#pragma unroll
                for (int x = 0; x < 5; x++) {
                    const int p = y * 5 + x;
#pragma unroll
                    for (int dy = -1; dy <= 1; dy++) {
                        if (y + dy < 0 || y + dy > 3) continue;
#pragma unroll
                        for (int dx = -1; dx <= 1; dx++) {
                            if (x + dx < 0 || x + dx > 4) continue;
                            fma2(acc[p], tv[(y + dy) * 5 + (x + dx)], w[(dy + 1) * 3 + (dx + 1)]);
                        }
                    }
                }
        }
        // gelu, row sums, analytic low-pass (only DC + ky=3 survive the mask)
        float rl[4], rh[4];
#pragma unroll
        for (int y = 0; y < 4; y++) {
            rl[y] = 0.f; rh[y] = 0.f;
#pragma unroll
            for (int x = 0; x < 5; x++) {
                float2 v = unpack2(acc[y * 5 + x]);
                rl[y] += gelu_f(v.x);
                rh[y] += gelu_f(v.y);
            }
        }
        float S0 = rl[0] + rl[1] + rl[2] + rl[3], A0 = rl[0] - rl[2], B0 = rl[1] - rl[3];
        float S1 = rh[0] + rh[1] + rh[2] + rh[3], A1 = rh[0] - rh[2], B1 = rh[1] - rh[3];
        float2 gy0 = make_float2(sqrtf((S0 + A0) * (S0 + A0) + B0 * B0) * 0.05f,
                                 sqrtf((S1 + A1) * (S1 + A1) + B1 * B1) * 0.05f);
        float2 gy1 = make_float2(sqrtf((S0 + B0) * (S0 + B0) + A0 * A0) * 0.05f,
                                 sqrtf((S1 + B1) * (S1 + B1) + A1 * A1) * 0.05f);
        float2 gy2 = make_float2(sqrtf((S0 - A0) * (S0 - A0) + B0 * B0) * 0.05f,
                                 sqrtf((S1 - A1) * (S1 - A1) + B1 * B1) * 0.05f);
        float2 gy3 = make_float2(sqrtf((S0 - B0) * (S0 - B0) + A0 * A0) * 0.05f,
                                 sqrtf((S1 - B1) * (S1 - B1) + A1 * A1) * 0.05f);
        float* gb = g_filt + (size_t)b * 4 * 768 + o;
        *(float2*)(gb) = gy0;
        *(float2*)(gb + 768) = gy1;
        *(float2*)(gb + 1536) = gy2;
        *(float2*)(gb + 2304) = gy3;
    }
}

// ---------------- K3: fused Q/K/V projection, M=8192 N=2304 K=768 + 5x replicated write ----
__global__ __launch_bounds__(256, 2) void k3_gemm(const float* __restrict__ wq,
                                                  const float* __restrict__ wk,
                                                  const float* __restrict__ wv,
                                                  float* __restrict__ out) {
    __shared__ __align__(16) float As[16][128];
    __shared__ __align__(16) float Bs[16][128];
    const int m0 = blockIdx.x * 128;
    const int n0 = blockIdx.y * 128;
    const int which = n0 / 768;
    const int nw0 = n0 - which * 768;
    const float* W = (which == 0) ? wq : ((which == 1) ? wk : wv);
    const int tid = threadIdx.x;
    const int f0 = tid * 2, f1 = f0 + 1;
    const int ar0 = f0 >> 2, ak0 = (f0 & 3) << 2;
    const int ar1 = f1 >> 2, ak1 = (f1 & 3) << 2;
    const float* Arow0 = g_filt + (size_t)(m0 + ar0) * 768 + ak0;
    const float* Arow1 = g_filt + (size_t)(m0 + ar1) * 768 + ak1;
    const float* Brow0 = W + (size_t)(nw0 + ar0) * 768 + ak0;
    const float* Brow1 = W + (size_t)(nw0 + ar1) * 768 + ak1;
    const int tx = tid & 15, ty = tid >> 4;

    u64 acc[8][4];
#pragma unroll
    for (int i = 0; i < 8; i++)
#pragma unroll
        for (int j = 0; j < 4; j++) acc[i][j] = 0ull;

    for (int k0i = 0; k0i < 768; k0i += 16) {
        float4 a0 = *(const float4*)(Arow0 + k0i);
        float4 a1 = *(const float4*)(Arow1 + k0i);
        float4 b0 = *(const float4*)(Brow0 + k0i);
        float4 b1 = *(const float4*)(Brow1 + k0i);
        __syncthreads();
        As[ak0 + 0][ar0] = a0.x; As[ak0 + 1][ar0] = a0.y; As[ak0 + 2][ar0] = a0.z; As[ak0 + 3][ar0] = a0.w;
        As[ak1 + 0][ar1] = a1.x; As[ak1 + 1][ar1] = a1.y; As[ak1 + 2][ar1] = a1.z; As[ak1 + 3][ar1] = a1.w;
        Bs[ak0 + 0][ar0] = b0.x; Bs[ak0 + 1][ar0] = b0.y; Bs[ak0 + 2][ar0] = b0.z; Bs[ak0 + 3][ar0] = b0.w;
        Bs[ak1 + 0][ar1] = b1.x; Bs[ak1 + 1][ar1] = b1.y; Bs[ak1 + 2][ar1] = b1.z; Bs[ak1 + 3][ar1] = b1.w;
        __syncthreads();
#pragma unroll
        for (int kk = 0; kk < 16; kk++) {
            float4 av0 = *(const float4*)&As[kk][ty * 8];
            float4 av1 = *(const float4*)&As[kk][ty * 8 + 4];
            ulonglong2 bb0 = *(const ulonglong2*)&Bs[kk][tx * 8];
            ulonglong2 bb1 = *(const ulonglong2*)&Bs[kk][tx * 8 + 4];
            u64 bp0 = bb0.x, bp1 = bb0.y, bp2 = bb1.x, bp3 = bb1.y;
            float am[8] = {av0.x, av0.y, av0.z, av0.w, av1.x, av1.y, av1.z, av1.w};
#pragma unroll
            for (int im = 0; im < 8; im++) {
                u64 s = splat2(am[im]);
                fma2(acc[im][0], s, bp0);
                fma2(acc[im][1], s, bp1);
                fma2(acc[im][2], s, bp2);
                fma2(acc[im][3], s, bp3);
            }
        }
    }

    float* outw = out + (size_t)which * OUTSZ;
#pragma unroll
    for (int im = 0; im < 8; im++) {
        int m = m0 + ty * 8 + im;
        int bb = m >> 2, y = m & 3;
        float vals[8];
#pragma unroll
        for (int j = 0; j < 4; j++) {
            float2 v = unpack2(acc[im][j]);
            vals[2 * j] = v.x;
            vals[2 * j + 1] = v.y;
        }
#pragma unroll
        for (int jq = 0; jq < 2; jq++) {
            int n = nw0 + tx * 8 + jq * 4;
            int nh = n >> 6, d = n & 63;
            float4 v = make_float4(vals[jq * 4], vals[jq * 4 + 1], vals[jq * 4 + 2], vals[jq * 4 + 3]);
            // token index = y*5 + xx, out[b][nh][tok][d], value identical across xx
            float* base = outw + (((size_t)bb * 12 + nh) * 20 + y * 5) * 64 + d;
#pragma unroll
            for (int xx = 0; xx < 5; xx++) *(float4*)(base + xx * 64) = v;
        }
    }
}

// ---------------- launch ----------------
extern "C" void kernel_launch(void* const* d_in, const int* in_sizes, int n_in,
                              void* d_out, int out_size) {
    const float* x  = (const float*)d_in[0];
    const float* w1 = (const float*)d_in[1];
    const float* w2 = (const float*)d_in[2];
    const float* wq = (const float*)d_in[3];
    const float* wk = (const float*)d_in[4];
    const float* wv = (const float*)d_in[5];
    float* out = (float*)d_out;

    const int smem_k2 = 2 * DH * NPOS * 4;   // 61440 bytes
    cudaFuncSetAttribute(k2_conv, cudaFuncAttributeMaxDynamicSharedMemorySize, smem_k2);

    k0_transpose<<<(DH * 9 * D + 255) / 256, 256>>>(w2);
    k1_gemm<<<dim3(320, 3), 256>>>(x, w1);
    k2_conv<<<1024, 256, smem_k2>>>();
    k3_gemm<<<dim3(64, 18), 256>>>(wq, wk, wv, out);
}

// round 2
// speedup vs baseline: 1.0023x; 1.0023x over previous
#include <cuda_runtime.h>
#include <math.h>

#define B_TOT 2048
#define D     768
#define DH    384
#define NPOS  20
#define OUTSZ (2048*12*20*64)   // per Q/K/V output: 31,457,280 floats

// ---------------- scratch (static device globals; no allocation) ----------------
__device__ float g_t1[B_TOT * NPOS * DH];   // gelu(1x1 conv) activations, [m=b*20+p][384]
__device__ float g_w2t[DH * 9 * D];         // w2 transposed to [(i*9+tap)*768 + o]
__device__ float g_filt[B_TOT * 4 * D];     // filtered rows, [(b*4+y)*768 + o]

typedef unsigned long long u64;

// ---------------- f32x2 helpers (packed fp32 pair FMA, sm_100+) ----------------
__device__ __forceinline__ u64 splat2(float v) {
    u64 r; unsigned u = __float_as_uint(v);
    asm("mov.b64 %0, {%1, %1};" : "=l"(r) : "r"(u));
    return r;
}
__device__ __forceinline__ void fma2(u64& a, u64 x, u64 y) {
    asm("fma.rn.f32x2 %0, %1, %2, %0;" : "+l"(a) : "l"(x), "l"(y));
}
__device__ __forceinline__ float2 unpack2(u64 v) {
    unsigned lo, hi;
    asm("mov.b64 {%0, %1}, %2;" : "=r"(lo), "=r"(hi) : "l"(v));
    return make_float2(__uint_as_float(lo), __uint_as_float(hi));
}
__device__ __forceinline__ float gelu_f(float v) {
    return 0.5f * v * (1.0f + erff(v * 0.7071067811865476f));
}

// ---------------- K0: transpose w2 (OIHW -> [i][tap][o]) ----------------
__global__ void k0_transpose(const float* __restrict__ w2) {
    int idx = blockIdx.x * 256 + threadIdx.x;
    if (idx >= DH * 9 * D) return;
    int o = idx % D;
    int r = idx / D;          // i*9 + tap
    int t = r % 9, i = r / 9;
    g_w2t[idx] = w2[(o * DH + i) * 9 + t];
}

// ---------------- K1: t1 = gelu(X @ W1^T), M=40960 N=384 K=768 ----------------
__global__ __launch_bounds__(256, 2) void k1_gemm(const float* __restrict__ X,
                                                  const float* __restrict__ W1) {
    __shared__ __align__(16) float As[16][128];
    __shared__ __align__(16) float Bs[16][128];
    const int m0 = blockIdx.x * 128;
    const int n0 = blockIdx.y * 128;
    const int tid = threadIdx.x;
    const int f0 = tid * 2, f1 = f0 + 1;
    const int ar0 = f0 >> 2, ak0 = (f0 & 3) << 2;
    const int ar1 = f1 >> 2, ak1 = (f1 & 3) << 2;
    const int mg0 = m0 + ar0, mg1 = m0 + ar1;
    // x row for m: token (1 + m%20) of batch m/20 -> offset (m + m/20 + 1)*768
    const float* Arow0 = X + (size_t)(mg0 + mg0 / 20 + 1) * 768 + ak0;
    const float* Arow1 = X + (size_t)(mg1 + mg1 / 20 + 1) * 768 + ak1;
    const float* Brow0 = W1 + (size_t)(n0 + ar0) * 768 + ak0;
    const float* Brow1 = W1 + (size_t)(n0 + ar1) * 768 + ak1;
    const int tx = tid & 15, ty = tid >> 4;

    u64 acc[8][4];
#pragma unroll
    for (int i = 0; i < 8; i++)
#pragma unroll
        for (int j = 0; j < 4; j++) acc[i][j] = 0ull;

    for (int k0i = 0; k0i < 768; k0i += 16) {
        float4 a0 = *(const float4*)(Arow0 + k0i);
        float4 a1 = *(const float4*)(Arow1 + k0i);
        float4 b0 = *(const float4*)(Brow0 + k0i);
        float4 b1 = *(const float4*)(Brow1 + k0i);
        __syncthreads();
        As[ak0 + 0][ar0] = a0.x; As[ak0 + 1][ar0] = a0.y; As[ak0 + 2][ar0] = a0.z; As[ak0 + 3][ar0] = a0.w;
        As[ak1 + 0][ar1] = a1.x; As[ak1 + 1][ar1] = a1.y; As[ak1 + 2][ar1] = a1.z; As[ak1 + 3][ar1] = a1.w;
        Bs[ak0 + 0][ar0] = b0.x; Bs[ak0 + 1][ar0] = b0.y; Bs[ak0 + 2][ar0] = b0.z; Bs[ak0 + 3][ar0] = b0.w;
        Bs[ak1 + 0][ar1] = b1.x; Bs[ak1 + 1][ar1] = b1.y; Bs[ak1 + 2][ar1] = b1.z; Bs[ak1 + 3][ar1] = b1.w;
        __syncthreads();
#pragma unroll
        for (int kk = 0; kk < 16; kk++) {
            float4 av0 = *(const float4*)&As[kk][ty * 8];
            float4 av1 = *(const float4*)&As[kk][ty * 8 + 4];
            ulonglong2 bb0 = *(const ulonglong2*)&Bs[kk][tx * 8];
            ulonglong2 bb1 = *(const ulonglong2*)&Bs[kk][tx * 8 + 4];
            u64 bp0 = bb0.x, bp1 = bb0.y, bp2 = bb1.x, bp3 = bb1.y;
            float am[8] = {av0.x, av0.y, av0.z, av0.w, av1.x, av1.y, av1.z, av1.w};
#pragma unroll
            for (int im = 0; im < 8; im++) {
                u64 s = splat2(am[im]);
                fma2(acc[im][0], s, bp0);
                fma2(acc[im][1], s, bp1);
                fma2(acc[im][2], s, bp2);
                fma2(acc[im][3], s, bp3);
            }
        }
    }
#pragma unroll
    for (int im = 0; im < 8; im++) {
        int m = m0 + ty * 8 + im;
        float vals[8];
#pragma unroll
        for (int j = 0; j < 4; j++) {
            float2 v = unpack2(acc[im][j]);
            vals[2 * j] = gelu_f(v.x);
            vals[2 * j + 1] = gelu_f(v.y);
        }
        float* dst = g_t1 + (size_t)m * 384 + n0 + tx * 8;
        *(float4*)dst = make_float4(vals[0], vals[1], vals[2], vals[3]);
        *(float4*)(dst + 4) = make_float4(vals[4], vals[5], vals[6], vals[7]);
    }
}

// ---------------- K2: conv3x3 + gelu + analytic FFT low-pass filter ----------------
// 2 batches per CTA (t1 tiles in smem), 256 threads = 64 o-pair lanes x {2 batches} x {2 o-halves}
__global__ __launch_bounds__(256, 1) void k2_conv() {
    extern __shared__ float s_t1[];   // [2][DH][NPOS]
    const int tid = threadIdx.x;
    const int bg0 = blockIdx.x * 2;
    for (int idx = tid; idx < 2 * NPOS * DH; idx += 256) {
        int b = idx / (NPOS * DH);
        int rem = idx - b * (NPOS * DH);
        int p = rem / DH;
        int i = rem - p * DH;
        s_t1[(b * DH + i) * NPOS + p] = g_t1[((size_t)(bg0 + b) * NPOS + p) * DH + i];
    }
    __syncthreads();
    const int lane = tid & 63;
    const int grp = tid >> 6;      // 0..3
    const int bi = grp & 1;
    const int oh = grp >> 1;       // which half of the 768 output channels
    const float* sb = s_t1 + bi * DH * NPOS;
    const int b = bg0 + bi;

    for (int ot = oh * 3; ot < oh * 3 + 3; ++ot) {
        const int o = ot * 128 + lane * 2;
        u64 acc[20];
#pragma unroll
        for (int p = 0; p < 20; p++) acc[p] = 0ull;
        const u64* wbase = (const u64*)(g_w2t + o);
        for (int i = 0; i < DH; i++) {
            const float* tr = sb + i * NPOS;
            float4 q0 = *(const float4*)tr;
            float4 q1 = *(const float4*)(tr + 4);
            float4 q2 = *(const float4*)(tr + 8);
            float4 q3 = *(const float4*)(tr + 12);
            float4 q4 = *(const float4*)(tr + 16);
            u64 tv[20];
            tv[0] = splat2(q0.x);  tv[1] = splat2(q0.y);  tv[2] = splat2(q0.z);  tv[3] = splat2(q0.w);
            tv[4] = splat2(q1.x);  tv[5] = splat2(q1.y);  tv[6] = splat2(q1.z);  tv[7] = splat2(q1.w);
            tv[8] = splat2(q2.x);  tv[9] = splat2(q2.y);  tv[10] = splat2(q2.z); tv[11] = splat2(q2.w);
            tv[12] = splat2(q3.x); tv[13] = splat2(q3.y); tv[14] = splat2(q3.z); tv[15] = splat2(q3.w);
            tv[16] = splat2(q4.x); tv[17] = splat2(q4.y); tv[18] = splat2(q4.z); tv[19] = splat2(q4.w);
            const u64* wr = wbase + (size_t)i * 9 * 384;  // (i*9+t)*768 floats
            u64 w[9];
#pragma unroll
            for (int t = 0; t < 9; t++) w[t] = wr[(size_t)t * 384];
#pragma unroll
            for (int y = 0; y < 4; y++)
#pragma unroll
                for (int x = 0; x < 5; x++) {
                    const int p = y * 5 + x;
#pragma unroll
                    for (int dy = -1; dy <= 1; dy++) {
                        if (y + dy < 0 || y + dy > 3) continue;
#pragma unroll
                        for (int dx = -1; dx <= 1; dx++) {
                            if (x + dx < 0 || x + dx > 4) continue;
                            fma2(acc[p], tv[(y + dy) * 5 + (x + dx)], w[(dy + 1) * 3 + (dx + 1)]);
                        }
                    }
                }
        }
        // gelu, row sums, analytic low-pass (only DC + ky=3 survive the mask)
        float rl[4], rh[4];
#pragma unroll
        for (int y = 0; y < 4; y++) {
            rl[y] = 0.f; rh[y] = 0.f;
#pragma unroll
            for (int x = 0; x < 5; x++) {
                float2 v = unpack2(acc[y * 5 + x]);
                rl[y] += gelu_f(v.x);
                rh[y] += gelu_f(v.y);
            }
        }
        float S0 = rl[0] + rl[1] + rl[2] + rl[3], A0 = rl[0] - rl[2], B0 = rl[1] - rl[3];
        float S1 = rh[0] + rh[1] + rh[2] + rh[3], A1 = rh[0] - rh[2], B1 = rh[1] - rh[3];
        float2 gy0 = make_float2(sqrtf((S0 + A0) * (S0 + A0) + B0 * B0) * 0.05f,
                                 sqrtf((S1 + A1) * (S1 + A1) + B1 * B1) * 0.05f);
        float2 gy1 = make_float2(sqrtf((S0 + B0) * (S0 + B0) + A0 * A0) * 0.05f,
                                 sqrtf((S1 + B1) * (S1 + B1) + A1 * A1) * 0.05f);
        float2 gy2 = make_float2(sqrtf((S0 - A0) * (S0 - A0) + B0 * B0) * 0.05f,
                                 sqrtf((S1 - A1) * (S1 - A1) + B1 * B1) * 0.05f);
        float2 gy3 = make_float2(sqrtf((S0 - B0) * (S0 - B0) + A0 * A0) * 0.05f,
                                 sqrtf((S1 - B1) * (S1 - B1) + A1 * A1) * 0.05f);
        float* gb = g_filt + (size_t)b * 4 * 768 + o;
        *(float2*)(gb) = gy0;
        *(float2*)(gb + 768) = gy1;
        *(float2*)(gb + 1536) = gy2;
        *(float2*)(gb + 2304) = gy3;
    }
}

// ---------------- K3: fused Q/K/V projection, M=8192 N=2304 K=768 + 5x replicated write ----
__global__ __launch_bounds__(256, 2) void k3_gemm(const float* __restrict__ wq,
                                                  const float* __restrict__ wk,
                                                  const float* __restrict__ wv,
                                                  float* __restrict__ out) {
    __shared__ __align__(16) float As[16][128];
    __shared__ __align__(16) float Bs[16][128];
    const int m0 = blockIdx.x * 128;
    const int n0 = blockIdx.y * 128;
    const int which = n0 / 768;
    const int nw0 = n0 - which * 768;
    const float* W = (which == 0) ? wq : ((which == 1) ? wk : wv);
    const int tid = threadIdx.x;
    const int f0 = tid * 2, f1 = f0 + 1;
    const int ar0 = f0 >> 2, ak0 = (f0 & 3) << 2;
    const int ar1 = f1 >> 2, ak1 = (f1 & 3) << 2;
    const float* Arow0 = g_filt + (size_t)(m0 + ar0) * 768 + ak0;
    const float* Arow1 = g_filt + (size_t)(m0 + ar1) * 768 + ak1;
    const float* Brow0 = W + (size_t)(nw0 + ar0) * 768 + ak0;
    const float* Brow1 = W + (size_t)(nw0 + ar1) * 768 + ak1;
    const int tx = tid & 15, ty = tid >> 4;

    u64 acc[8][4];
#pragma unroll
    for (int i = 0; i < 8; i++)
#pragma unroll
        for (int j = 0; j < 4; j++) acc[i][j] = 0ull;

    for (int k0i = 0; k0i < 768; k0i += 16) {
        float4 a0 = *(const float4*)(Arow0 + k0i);
        float4 a1 = *(const float4*)(Arow1 + k0i);
        float4 b0 = *(const float4*)(Brow0 + k0i);
        float4 b1 = *(const float4*)(Brow1 + k0i);
        __syncthreads();
        As[ak0 + 0][ar0] = a0.x; As[ak0 + 1][ar0] = a0.y; As[ak0 + 2][ar0] = a0.z; As[ak0 + 3][ar0] = a0.w;
        As[ak1 + 0][ar1] = a1.x; As[ak1 + 1][ar1] = a1.y; As[ak1 + 2][ar1] = a1.z; As[ak1 + 3][ar1] = a1.w;
        Bs[ak0 + 0][ar0] = b0.x; Bs[ak0 + 1][ar0] = b0.y; Bs[ak0 + 2][ar0] = b0.z; Bs[ak0 + 3][ar0] = b0.w;
        Bs[ak1 + 0][ar1] = b1.x; Bs[ak1 + 1][ar1] = b1.y; Bs[ak1 + 2][ar1] = b1.z; Bs[ak1 + 3][ar1] = b1.w;
        __syncthreads();
#pragma unroll
        for (int kk = 0; kk < 16; kk++) {
            float4 av0 = *(const float4*)&As[kk][ty * 8];
            float4 av1 = *(const float4*)&As[kk][ty * 8 + 4];
            ulonglong2 bb0 = *(const ulonglong2*)&Bs[kk][tx * 8];
            ulonglong2 bb1 = *(const ulonglong2*)&Bs[kk][tx * 8 + 4];
            u64 bp0 = bb0.x, bp1 = bb0.y, bp2 = bb1.x, bp3 = bb1.y;
            float am[8] = {av0.x, av0.y, av0.z, av0.w, av1.x, av1.y, av1.z, av1.w};
#pragma unroll
            for (int im = 0; im < 8; im++) {
                u64 s = splat2(am[im]);
                fma2(acc[im][0], s, bp0);
                fma2(acc[im][1], s, bp1);
                fma2(acc[im][2], s, bp2);
                fma2(acc[im][3], s, bp3);
            }
        }
    }

    float* outw = out + (size_t)which * OUTSZ;
#pragma unroll
    for (int im = 0; im < 8; im++) {
        int m = m0 + ty * 8 + im;
        int bb = m >> 2, y = m & 3;
        float vals[8];
#pragma unroll
        for (int j = 0; j < 4; j++) {
            float2 v = unpack2(acc[im][j]);
            vals[2 * j] = v.x;
            vals[2 * j + 1] = v.y;
        }
#pragma unroll
        for (int jq = 0; jq < 2; jq++) {
            int n = nw0 + tx * 8 + jq * 4;
            int nh = n >> 6, d = n & 63;
            float4 v = make_float4(vals[jq * 4], vals[jq * 4 + 1], vals[jq * 4 + 2], vals[jq * 4 + 3]);
            // token index = y*5 + xx, out[b][nh][tok][d], value identical across xx
            float* base = outw + (((size_t)bb * 12 + nh) * 20 + y * 5) * 64 + d;
#pragma unroll
            for (int xx = 0; xx < 5; xx++) *(float4*)(base + xx * 64) = v;
        }
    }
}

// ---------------- launch ----------------
extern "C" void kernel_launch(void* const* d_in, const int* in_sizes, int n_in,
                              void* d_out, int out_size) {
    const float* x  = (const float*)d_in[0];
    const float* w1 = (const float*)d_in[1];
    const float* w2 = (const float*)d_in[2];
    const float* wq = (const float*)d_in[3];
    const float* wk = (const float*)d_in[4];
    const float* wv = (const float*)d_in[5];
    float* out = (float*)d_out;

    const int smem_k2 = 2 * DH * NPOS * 4;   // 61440 bytes
    cudaFuncSetAttribute(k2_conv, cudaFuncAttributeMaxDynamicSharedMemorySize, smem_k2);

    k0_transpose<<<(DH * 9 * D + 255) / 256, 256>>>(w2);
    k1_gemm<<<dim3(320, 3), 256>>>(x, w1);
    k2_conv<<<1024, 256, smem_k2>>>();
    k3_gemm<<<dim3(64, 18), 256>>>(wq, wk, wv, out);
}

// round 3
// speedup vs baseline: 1.0029x; 1.0006x over previous
#include <cuda_runtime.h>
#include <math.h>

#define B_TOT 2048
#define D     768
#define DH    384
#define NPOS  20
#define OUTSZ (2048*12*20*64)   // per Q/K/V output: 31,457,280 floats

// ---------------- scratch (static device globals; no allocation) ----------------
__device__ float g_t1[B_TOT * NPOS * DH];   // gelu(1x1 conv) activations, [m=b*20+p][384]
__device__ float g_w2t[DH * 9 * D];         // w2 transposed to [(i*9+tap)*768 + o]
__device__ float g_filt[B_TOT * 4 * D];     // filtered rows, [(b*4+y)*768 + o]

typedef unsigned long long u64;

// ---------------- f32x2 helpers (packed fp32 pair FMA, sm_100+) ----------------
__device__ __forceinline__ u64 splat2(float v) {
    u64 r; unsigned u = __float_as_uint(v);
    asm("mov.b64 %0, {%1, %1};" : "=l"(r) : "r"(u));
    return r;
}
__device__ __forceinline__ void fma2(u64& a, u64 x, u64 y) {
    asm("fma.rn.f32x2 %0, %1, %2, %0;" : "+l"(a) : "l"(x), "l"(y));
}
__device__ __forceinline__ float2 unpack2(u64 v) {
    unsigned lo, hi;
    asm("mov.b64 {%0, %1}, %2;" : "=r"(lo), "=r"(hi) : "l"(v));
    return make_float2(__uint_as_float(lo), __uint_as_float(hi));
}
__device__ __forceinline__ float gelu_f(float v) {
    return 0.5f * v * (1.0f + erff(v * 0.7071067811865476f));
}

// ---------------- K0: transpose w2 (OIHW -> [i][tap][o]) ----------------
__global__ void k0_transpose(const float* __restrict__ w2) {
    int idx = blockIdx.x * 256 + threadIdx.x;
    if (idx >= DH * 9 * D) return;
    int o = idx % D;
    int r = idx / D;          // i*9 + tap
    int t = r % 9, i = r / 9;
    g_w2t[idx] = w2[(o * DH + i) * 9 + t];
}

// ---------------- K1: t1 = gelu(X @ W1^T), M=40960 N=384 K=768 ----------------
__global__ __launch_bounds__(256, 2) void k1_gemm(const float* __restrict__ X,
                                                  const float* __restrict__ W1) {
    __shared__ __align__(16) float As[16][128];
    __shared__ __align__(16) float Bs[16][128];
    const int m0 = blockIdx.x * 128;
    const int n0 = blockIdx.y * 128;
    const int tid = threadIdx.x;
    const int f0 = tid * 2, f1 = f0 + 1;
    const int ar0 = f0 >> 2, ak0 = (f0 & 3) << 2;
    const int ar1 = f1 >> 2, ak1 = (f1 & 3) << 2;
    const int mg0 = m0 + ar0, mg1 = m0 + ar1;
    // x row for m: token (1 + m%20) of batch m/20 -> offset (m + m/20 + 1)*768
    const float* Arow0 = X + (size_t)(mg0 + mg0 / 20 + 1) * 768 + ak0;
    const float* Arow1 = X + (size_t)(mg1 + mg1 / 20 + 1) * 768 + ak1;
    const float* Brow0 = W1 + (size_t)(n0 + ar0) * 768 + ak0;
    const float* Brow1 = W1 + (size_t)(n0 + ar1) * 768 + ak1;
    const int tx = tid & 15, ty = tid >> 4;

    u64 acc[8][4];
#pragma unroll
    for (int i = 0; i < 8; i++)
#pragma unroll
        for (int j = 0; j < 4; j++) acc[i][j] = 0ull;

    for (int k0i = 0; k0i < 768; k0i += 16) {
        float4 a0 = *(const float4*)(Arow0 + k0i);
        float4 a1 = *(const float4*)(Arow1 + k0i);
        float4 b0 = *(const float4*)(Brow0 + k0i);
        float4 b1 = *(const float4*)(Brow1 + k0i);
        __syncthreads();
        As[ak0 + 0][ar0] = a0.x; As[ak0 + 1][ar0] = a0.y; As[ak0 + 2][ar0] = a0.z; As[ak0 + 3][ar0] = a0.w;
        As[ak1 + 0][ar1] = a1.x; As[ak1 + 1][ar1] = a1.y; As[ak1 + 2][ar1] = a1.z; As[ak1 + 3][ar1] = a1.w;
        Bs[ak0 + 0][ar0] = b0.x; Bs[ak0 + 1][ar0] = b0.y; Bs[ak0 + 2][ar0] = b0.z; Bs[ak0 + 3][ar0] = b0.w;
        Bs[ak1 + 0][ar1] = b1.x; Bs[ak1 + 1][ar1] = b1.y; Bs[ak1 + 2][ar1] = b1.z; Bs[ak1 + 3][ar1] = b1.w;
        __syncthreads();
#pragma unroll
        for (int kk = 0; kk < 16; kk++) {
            float4 av0 = *(const float4*)&As[kk][ty * 8];
            float4 av1 = *(const float4*)&As[kk][ty * 8 + 4];
            ulonglong2 bb0 = *(const ulonglong2*)&Bs[kk][tx * 8];
            ulonglong2 bb1 = *(const ulonglong2*)&Bs[kk][tx * 8 + 4];
            u64 bp0 = bb0.x, bp1 = bb0.y, bp2 = bb1.x, bp3 = bb1.y;
            float am[8] = {av0.x, av0.y, av0.z, av0.w, av1.x, av1.y, av1.z, av1.w};
#pragma unroll
            for (int im = 0; im < 8; im++) {
                u64 s = splat2(am[im]);
                fma2(acc[im][0], s, bp0);
                fma2(acc[im][1], s, bp1);
                fma2(acc[im][2], s, bp2);
                fma2(acc[im][3], s, bp3);
            }
        }
    }
#pragma unroll
    for (int im = 0; im < 8; im++) {
        int m = m0 + ty * 8 + im;
        float vals[8];
#pragma unroll
        for (int j = 0; j < 4; j++) {
            float2 v = unpack2(acc[im][j]);
            vals[2 * j] = gelu_f(v.x);
            vals[2 * j + 1] = gelu_f(v.y);
        }
        float* dst = g_t1 + (size_t)m * 384 + n0 + tx * 8;
        *(float4*)dst = make_float4(vals[0], vals[1], vals[2], vals[3]);
        *(float4*)(dst + 4) = make_float4(vals[4], vals[5], vals[6], vals[7]);
    }
}

// ---------------- K2: conv3x3 + gelu + analytic FFT low-pass filter ----------------
// 2 batches per CTA (t1 tiles in smem), 256 threads = 64 o-pair lanes x {2 batches} x {2 o-halves}
__global__ __launch_bounds__(256, 1) void k2_conv() {
    extern __shared__ float s_t1[];   // [2][DH][NPOS]
    const int tid = threadIdx.x;
    const int bg0 = blockIdx.x * 2;
    for (int idx = tid; idx < 2 * NPOS * DH; idx += 256) {
        int b = idx / (NPOS * DH);
        int rem = idx - b * (NPOS * DH);
        int p = rem / DH;
        int i = rem - p * DH;
        s_t1[(b * DH + i) * NPOS + p] = g_t1[((size_t)(bg0 + b) * NPOS + p) * DH + i];
    }
    __syncthreads();
    const int lane = tid & 63;
    const int grp = tid >> 6;      // 0..3
    const int bi = grp & 1;
    const int oh = grp >> 1;       // which half of the 768 output channels
    const float* sb = s_t1 + bi * DH * NPOS;
    const int b = bg0 + bi;

    for (int ot = oh * 3; ot < oh * 3 + 3; ++ot) {
        const int o = ot * 128 + lane * 2;
        u64 acc[20];
#pragma unroll
        for (int p = 0; p < 20; p++) acc[p] = 0ull;
        const u64* wbase = (const u64*)(g_w2t + o);
        for (int i = 0; i < DH; i++) {
            const float* tr = sb + i * NPOS;
            float4 q0 = *(const float4*)tr;
            float4 q1 = *(const float4*)(tr + 4);
            float4 q2 = *(const float4*)(tr + 8);
            float4 q3 = *(const float4*)(tr + 12);
            float4 q4 = *(const float4*)(tr + 16);
            u64 tv[20];
            tv[0] = splat2(q0.x);  tv[1] = splat2(q0.y);  tv[2] = splat2(q0.z);  tv[3] = splat2(q0.w);
            tv[4] = splat2(q1.x);  tv[5] = splat2(q1.y);  tv[6] = splat2(q1.z);  tv[7] = splat2(q1.w);
            tv[8] = splat2(q2.x);  tv[9] = splat2(q2.y);  tv[10] = splat2(q2.z); tv[11] = splat2(q2.w);
            tv[12] = splat2(q3.x); tv[13] = splat2(q3.y); tv[14] = splat2(q3.z); tv[15] = splat2(q3.w);
            tv[16] = splat2(q4.x); tv[17] = splat2(q4.y); tv[18] = splat2(q4.z); tv[19] = splat2(q4.w);
            const u64* wr = wbase + (size_t)i * 9 * 384;  // (i*9+t)*768 floats
            u64 w[9];
#pragma unroll
            for (int t = 0; t < 9; t++) w[t] = wr[(size_t)t * 384];
#pragma unroll
            for (int y = 0; y < 4; y++)
#pragma unroll
                for (int x = 0; x < 5; x++) {
                    const int p = y * 5 + x;
#pragma unroll
                    for (int dy = -1; dy <= 1; dy++) {
                        if (y + dy < 0 || y + dy > 3) continue;
#pragma unroll
                        for (int dx = -1; dx <= 1; dx++) {
                            if (x + dx < 0 || x + dx > 4) continue;
                            fma2(acc[p], tv[(y + dy) * 5 + (x + dx)], w[(dy + 1) * 3 + (dx + 1)]);
                        }
                    }
                }
        }
        // gelu, row sums, analytic low-pass (only DC + ky=3 survive the mask)
        float rl[4], rh[4];
#pragma unroll
        for (int y = 0; y < 4; y++) {
            rl[y] = 0.f; rh[y] = 0.f;
#pragma unroll
            for (int x = 0; x < 5; x++) {
                float2 v = unpack2(acc[y * 5 + x]);
                rl[y] += gelu_f(v.x);
                rh[y] += gelu_f(v.y);
            }
        }
        float S0 = rl[0] + rl[1] + rl[2] + rl[3], A0 = rl[0] - rl[2], B0 = rl[1] - rl[3];
        float S1 = rh[0] + rh[1] + rh[2] + rh[3], A1 = rh[0] - rh[2], B1 = rh[1] - rh[3];
        float2 gy0 = make_float2(sqrtf((S0 + A0) * (S0 + A0) + B0 * B0) * 0.05f,
                                 sqrtf((S1 + A1) * (S1 + A1) + B1 * B1) * 0.05f);
        float2 gy1 = make_float2(sqrtf((S0 + B0) * (S0 + B0) + A0 * A0) * 0.05f,
                                 sqrtf((S1 + B1) * (S1 + B1) + A1 * A1) * 0.05f);
        float2 gy2 = make_float2(sqrtf((S0 - A0) * (S0 - A0) + B0 * B0) * 0.05f,
                                 sqrtf((S1 - A1) * (S1 - A1) + B1 * B1) * 0.05f);
        float2 gy3 = make_float2(sqrtf((S0 - B0) * (S0 - B0) + A0 * A0) * 0.05f,
                                 sqrtf((S1 - B1) * (S1 - B1) + A1 * A1) * 0.05f);
        float* gb = g_filt + (size_t)b * 4 * 768 + o;
        *(float2*)(gb) = gy0;
        *(float2*)(gb + 768) = gy1;
        *(float2*)(gb + 1536) = gy2;
        *(float2*)(gb + 2304) = gy3;
    }
}

// ---------------- K3: fused Q/K/V projection, M=8192 N=2304 K=768 + 5x replicated write ----
__global__ __launch_bounds__(256, 2) void k3_gemm(const float* __restrict__ wq,
                                                  const float* __restrict__ wk,
                                                  const float* __restrict__ wv,
                                                  float* __restrict__ out) {
    __shared__ __align__(16) float As[16][128];
    __shared__ __align__(16) float Bs[16][128];
    const int m0 = blockIdx.x * 128;
    const int n0 = blockIdx.y * 128;
    const int which = n0 / 768;
    const int nw0 = n0 - which * 768;
    const float* W = (which == 0) ? wq : ((which == 1) ? wk : wv);
    const int tid = threadIdx.x;
    const int f0 = tid * 2, f1 = f0 + 1;
    const int ar0 = f0 >> 2, ak0 = (f0 & 3) << 2;
    const int ar1 = f1 >> 2, ak1 = (f1 & 3) << 2;
    const float* Arow0 = g_filt + (size_t)(m0 + ar0) * 768 + ak0;
    const float* Arow1 = g_filt + (size_t)(m0 + ar1) * 768 + ak1;
    const float* Brow0 = W + (size_t)(nw0 + ar0) * 768 + ak0;
    const float* Brow1 = W + (size_t)(nw0 + ar1) * 768 + ak1;
    const int tx = tid & 15, ty = tid >> 4;

    u64 acc[8][4];
#pragma unroll
    for (int i = 0; i < 8; i++)
#pragma unroll
        for (int j = 0; j < 4; j++) acc[i][j] = 0ull;

    for (int k0i = 0; k0i < 768; k0i += 16) {
        float4 a0 = *(const float4*)(Arow0 + k0i);
        float4 a1 = *(const float4*)(Arow1 + k0i);
        float4 b0 = *(const float4*)(Brow0 + k0i);
        float4 b1 = *(const float4*)(Brow1 + k0i);
        __syncthreads();
        As[ak0 + 0][ar0] = a0.x; As[ak0 + 1][ar0] = a0.y; As[ak0 + 2][ar0] = a0.z; As[ak0 + 3][ar0] = a0.w;
        As[ak1 + 0][ar1] = a1.x; As[ak1 + 1][ar1] = a1.y; As[ak1 + 2][ar1] = a1.z; As[ak1 + 3][ar1] = a1.w;
        Bs[ak0 + 0][ar0] = b0.x; Bs[ak0 + 1][ar0] = b0.y; Bs[ak0 + 2][ar0] = b0.z; Bs[ak0 + 3][ar0] = b0.w;
        Bs[ak1 + 0][ar1] = b1.x; Bs[ak1 + 1][ar1] = b1.y; Bs[ak1 + 2][ar1] = b1.z; Bs[ak1 + 3][ar1] = b1.w;
        __syncthreads();
#pragma unroll
        for (int kk = 0; kk < 16; kk++) {
            float4 av0 = *(const float4*)&As[kk][ty * 8];
            float4 av1 = *(const float4*)&As[kk][ty * 8 + 4];
            ulonglong2 bb0 = *(const ulonglong2*)&Bs[kk][tx * 8];
            ulonglong2 bb1 = *(const ulonglong2*)&Bs[kk][tx * 8 + 4];
            u64 bp0 = bb0.x, bp1 = bb0.y, bp2 = bb1.x, bp3 = bb1.y;
            float am[8] = {av0.x, av0.y, av0.z, av0.w, av1.x, av1.y, av1.z, av1.w};
#pragma unroll
            for (int im = 0; im < 8; im++) {
                u64 s = splat2(am[im]);
                fma2(acc[im][0], s, bp0);
                fma2(acc[im][1], s, bp1);
                fma2(acc[im][2], s, bp2);
                fma2(acc[im][3], s, bp3);
            }
        }
    }

    float* outw = out + (size_t)which * OUTSZ;
#pragma unroll
    for (int im = 0; im < 8; im++) {
        int m = m0 + ty * 8 + im;
        int bb = m >> 2, y = m & 3;
        float vals[8];
#pragma unroll
        for (int j = 0; j < 4; j++) {
            float2 v = unpack2(acc[im][j]);
            vals[2 * j] = v.x;
            vals[2 * j + 1] = v.y;
        }
#pragma unroll
        for (int jq = 0; jq < 2; jq++) {
            int n = nw0 + tx * 8 + jq * 4;
            int nh = n >> 6, d = n & 63;
            float4 v = make_float4(vals[jq * 4], vals[jq * 4 + 1], vals[jq * 4 + 2], vals[jq * 4 + 3]);
            // token index = y*5 + xx, out[b][nh][tok][d], value identical across xx
            float* base = outw + (((size_t)bb * 12 + nh) * 20 + y * 5) * 64 + d;
#pragma unroll
            for (int xx = 0; xx < 5; xx++) *(float4*)(base + xx * 64) = v;
        }
    }
}

// ---------------- launch ----------------
extern "C" void kernel_launch(void* const* d_in, const int* in_sizes, int n_in,
                              void* d_out, int out_size) {
    const float* x  = (const float*)d_in[0];
    const float* w1 = (const float*)d_in[1];
    const float* w2 = (const float*)d_in[2];
    const float* wq = (const float*)d_in[3];
    const float* wk = (const float*)d_in[4];
    const float* wv = (const float*)d_in[5];
    float* out = (float*)d_out;

    const int smem_k2 = 2 * DH * NPOS * 4;   // 61440 bytes
    cudaFuncSetAttribute(k2_conv, cudaFuncAttributeMaxDynamicSharedMemorySize, smem_k2);

    k0_transpose<<<(DH * 9 * D + 255) / 256, 256>>>(w2);
    k1_gemm<<<dim3(320, 3), 256>>>(x, w1);
    k2_conv<<<1024, 256, smem_k2>>>();
    k3_gemm<<<dim3(64, 18), 256>>>(wq, wk, wv, out);
}

// round 5
// speedup vs baseline: 2.2817x; 2.2751x over previous
#include <cuda_runtime.h>
#include <math.h>
#include <stdint.h>

typedef uint32_t u32;

#define OUTSZ (2048u*12u*20u*64u)

// ---------------- static device scratch ----------------
__device__ __align__(256) float g_xr [40960u*768u];   // X packed (CLS dropped), tf32-rounded
__device__ __align__(256) float g_w1r[384u*768u];
__device__ __align__(256) float g_wqr[768u*768u];
__device__ __align__(256) float g_wkr[768u*768u];
__device__ __align__(256) float g_wvr[768u*768u];
__device__ __align__(256) float g_w2t[768u*3456u];    // w2 -> [o][tap*384+i], rounded
__device__ __align__(256) float g_t1 [40960u*384u];   // gelu(conv1x1), rounded
__device__ __align__(256) float g_t2 [40960u*768u];   // conv3x3 raw
__device__ __align__(256) float g_filt[8192u*768u];   // filtered rows, rounded

// ---------------- helpers ----------------
__device__ __forceinline__ u32 smem_u32(const void* p) {
    u32 a;
    asm("{ .reg .u64 t; cvta.to.shared.u64 t, %1; cvt.u32.u64 %0, t; }" : "=r"(a) : "l"(p));
    return a;
}
__device__ __forceinline__ float tf32r(float x) {
    float y; asm("cvt.rna.tf32.f32 %0, %1;" : "=f"(y) : "f"(x)); return y;
}
__device__ __forceinline__ float gelu_f(float v) {
    return 0.5f * v * (1.0f + erff(v * 0.7071067811865476f));
}

#define CPA(sa, ga, sz) asm volatile("cp.async.cg.shared.global [%0], [%1], 16, %2;" :: "r"(sa), "l"(ga), "r"(sz) : "memory")
#define CPC()  asm volatile("cp.async.commit_group;" ::: "memory")
#define CPW(n) asm volatile("cp.async.wait_group %0;" :: "n"(n) : "memory")

__device__ __forceinline__ void mma8(float* c, const u32* a, const u32* b) {
    asm volatile("mma.sync.aligned.m16n8k8.row.col.f32.tf32.tf32.f32 "
        "{%0,%1,%2,%3}, {%4,%5,%6,%7}, {%8,%9}, {%0,%1,%2,%3};"
        : "+f"(c[0]), "+f"(c[1]), "+f"(c[2]), "+f"(c[3])
        : "r"(a[0]), "r"(a[1]), "r"(a[2]), "r"(a[3]), "r"(b[0]), "r"(b[1]));
}

// ---------------- prep kernels ----------------
__global__ void krnd_x(const float* __restrict__ X) {
    int idx = blockIdx.x * 256 + threadIdx.x;      // over 40960*192 float4s
    if (idx >= 40960 * 192) return;
    int m = idx / 192, c = idx - m * 192;
    float4 v = *(const float4*)(X + ((size_t)m + m / 20 + 1) * 768 + c * 4);
    *(float4*)(g_xr + (size_t)m * 768 + c * 4) =
        make_float4(tf32r(v.x), tf32r(v.y), tf32r(v.z), tf32r(v.w));
}
__global__ void krnd_w(const float* __restrict__ src, int n4, int sel) {
    int idx = blockIdx.x * 256 + threadIdx.x;
    if (idx >= n4) return;
    float* dst = (sel == 0) ? g_w1r : (sel == 1) ? g_wqr : (sel == 2) ? g_wkr : g_wvr;
    float4 v = *(const float4*)(src + (size_t)idx * 4);
    *(float4*)(dst + (size_t)idx * 4) = make_float4(tf32r(v.x), tf32r(v.y), tf32r(v.z), tf32r(v.w));
}
__global__ void k0_w2t(const float* __restrict__ w2) {
    int idx = blockIdx.x * 256 + threadIdx.x;      // over 768*3456
    if (idx >= 768 * 3456) return;
    int o = idx / 3456, r = idx - o * 3456;
    int t = r / 384, i = r - t * 384;
    g_w2t[idx] = tf32r(w2[((size_t)o * 384 + i) * 9 + t]);
}

// ---------------- filter: gelu + analytic FFT low-pass (2 surviving freqs) ----------------
__global__ void kfilter() {
    int idx = blockIdx.x * 256 + threadIdx.x;      // over 2048*192
    if (idx >= 2048 * 192) return;
    int b = idx / 192, oq = idx - b * 192;
    const float* src = g_t2 + (size_t)b * (20 * 768) + oq * 4;
    float ry[4][4];
#pragma unroll
    for (int y = 0; y < 4; y++) {
        float a0 = 0.f, a1 = 0.f, a2 = 0.f, a3 = 0.f;
#pragma unroll
        for (int x = 0; x < 5; x++) {
            float4 v = *(const float4*)(src + (size_t)(y * 5 + x) * 768);
            a0 += gelu_f(v.x); a1 += gelu_f(v.y); a2 += gelu_f(v.z); a3 += gelu_f(v.w);
        }
        ry[y][0] = a0; ry[y][1] = a1; ry[y][2] = a2; ry[y][3] = a3;
    }
    float o[4][4];
#pragma unroll
    for (int j = 0; j < 4; j++) {
        float S  = ry[0][j] + ry[1][j] + ry[2][j] + ry[3][j];
        float A  = ry[0][j] - ry[2][j];
        float Bv = ry[1][j] - ry[3][j];
        o[0][j] = tf32r(sqrtf((S + A) * (S + A) + Bv * Bv) * 0.05f);
        o[1][j] = tf32r(sqrtf((S + Bv) * (S + Bv) + A * A) * 0.05f);
        o[2][j] = tf32r(sqrtf((S - A) * (S - A) + Bv * Bv) * 0.05f);
        o[3][j] = tf32r(sqrtf((S - Bv) * (S - Bv) + A * A) * 0.05f);
    }
    float* dst = g_filt + (size_t)b * 4 * 768 + oq * 4;
#pragma unroll
    for (int y = 0; y < 4; y++)
        *(float4*)(dst + (size_t)y * 768) = make_float4(o[y][0], o[y][1], o[y][2], o[y][3]);
}

// ---------------- tf32 mma.sync GEMM ----------------
// MODE 0: g_t1 = tf32r(gelu(g_xr @ g_w1r^T))             M=40960 N=384  K=768   BN=128
// MODE 1: g_t2 = im2col(g_t1) @ g_w2t^T  (implicit)      M=40960 N=768  K=3456  BN=256
// MODE 2: out  = g_filt @ {wq|wk|wv}^T, 5x token scatter M=8192  N=2304 K=768   BN=256
// BM=128, BK=32, 3-stage cp.async, 8 warps 2(M)x4(N), warp tile 64 x (BN/4)
template<int MODE, int BN>
__global__ __launch_bounds__(256, 1) void gemm_mma(float* __restrict__ Cout) {
    constexpr int KTOT = (MODE == 1) ? 3456 : 768;
    constexpr int L = KTOT / 32;
    constexpr int LDS_ = 36;                       // floats per smem row (bank-conflict free)
    constexpr int ASMF = 128 * LDS_;               // A stage floats
    constexpr int BSMF = BN * LDS_;
    constexpr int STGF = ASMF + BSMF;
    constexpr int NB = BN / 32;                    // B float4 loads per thread
    constexpr int WN = BN / 4;                     // warp n extent
    constexpr int NT = WN / 8;                     // n8 tiles per warp
    constexpr int MT = 4;                          // m16 tiles per warp (64)

    extern __shared__ float smf[];
    const u32 sbase = smem_u32(smf);
    const int tid = threadIdx.x, wid = tid >> 5, lane = tid & 31;
    const int wm = wid >> 2, wn = wid & 3;
    const int lr = lane >> 2, lc = lane & 3;
    const int n0 = blockIdx.x * BN, m0 = blockIdx.y * 128;

    int which = 0, nw0 = n0;
    const float* Bb;
    if (MODE == 2) {
        which = n0 / 768; nw0 = n0 - which * 768;
        Bb = (which == 0) ? g_wqr : (which == 1) ? g_wkr : g_wvr;
    } else {
        Bb = (MODE == 0) ? g_w1r : g_w2t;
    }
    const float* Ab = (MODE == 0) ? g_xr : (MODE == 1) ? g_t1 : g_filt;

    // per-thread cp.async slots
    u32 saoff[4]; const float* aptr[4];
    int ab20[4], ay[4], ax[4], akf[4];
#pragma unroll
    for (int v = 0; v < 4; v++) {
        int idx = v * 256 + tid, r = idx >> 3, c4 = idx & 7;   // r: 0..127
        saoff[v] = (u32)(r * LDS_ + c4 * 4) * 4u;
        if (MODE != 1) {
            aptr[v] = Ab + (size_t)(m0 + r) * 768 + c4 * 4;
        } else {
            int m = m0 + r, b = m / 20, p = m - b * 20;
            ab20[v] = b * 20; ay[v] = p / 5; ax[v] = p - (p / 5) * 5; akf[v] = c4 * 4;
        }
    }
    u32 sboff[NB]; const float* bptr[NB];
#pragma unroll
    for (int v = 0; v < NB; v++) {
        int idx = v * 256 + tid, r = idx >> 3, c4 = idx & 7;   // r: 0..BN-1
        sboff[v] = (u32)(ASMF + r * LDS_ + c4 * 4) * 4u;
        bptr[v] = Bb + (size_t)(nw0 + r) * KTOT + c4 * 4;
    }

    auto load = [&](int c, int s) {
        u32 base = sbase + (u32)(s * STGF) * 4u;
        if (MODE == 1) {
            int tap = c / 12, kk = (c - tap * 12) * 32;
            int dy = tap / 3 - 1, dx = tap - (tap / 3) * 3 - 1;
#pragma unroll
            for (int v = 0; v < 4; v++) {
                int ny = ay[v] + dy, nx = ax[v] + dx;
                bool ok = ((unsigned)ny < 4u) && ((unsigned)nx < 5u);
                const float* src = g_t1 + ((size_t)(ab20[v] + ny * 5 + nx) * 384 + kk + akf[v]);
                CPA(base + saoff[v], ok ? src : (const float*)g_t1, ok ? 16u : 0u);
            }
        } else {
#pragma unroll
            for (int v = 0; v < 4; v++) CPA(base + saoff[v], aptr[v] + (size_t)c * 32, 16u);
        }
#pragma unroll
        for (int v = 0; v < NB; v++) CPA(base + sboff[v], bptr[v] + (size_t)c * 32, 16u);
        CPC();
    };

    float acc[MT][NT][4];
#pragma unroll
    for (int i = 0; i < MT; i++)
#pragma unroll
        for (int j = 0; j < NT; j++)
#pragma unroll
            for (int q = 0; q < 4; q++) acc[i][j][q] = 0.f;

    load(0, 0);
    load(1, 1);

    for (int c = 0; c < L; c++) {
        int s = c % 3;
        CPW(1);
        __syncthreads();
        if (c + 2 < L) load(c + 2, (c + 2) % 3); else CPC();

        const float* As = smf + s * STGF;
        const float* Bs = smf + s * STGF + ASMF;
#pragma unroll
        for (int ks = 0; ks < 4; ks++) {
            u32 af[MT][4];
#pragma unroll
            for (int mt = 0; mt < MT; mt++) {
                int row = wm * 64 + mt * 16 + lr, col = ks * 8 + lc;
                af[mt][0] = __float_as_uint(As[row * LDS_ + col]);
                af[mt][1] = __float_as_uint(As[(row + 8) * LDS_ + col]);
                af[mt][2] = __float_as_uint(As[row * LDS_ + col + 4]);
                af[mt][3] = __float_as_uint(As[(row + 8) * LDS_ + col + 4]);
            }
            u32 bf[NT][2];
#pragma unroll
            for (int nt = 0; nt < NT; nt++) {
                int rn = wn * WN + nt * 8 + lr, col = ks * 8 + lc;
                bf[nt][0] = __float_as_uint(Bs[rn * LDS_ + col]);
                bf[nt][1] = __float_as_uint(Bs[rn * LDS_ + col + 4]);
            }
#pragma unroll
            for (int mt = 0; mt < MT; mt++)
#pragma unroll
                for (int nt = 0; nt < NT; nt++)
                    mma8(acc[mt][nt], af[mt], bf[nt]);
        }
        __syncthreads();
    }

    // ---------------- epilogue ----------------
#pragma unroll
    for (int mt = 0; mt < MT; mt++) {
        int r0 = m0 + wm * 64 + mt * 16 + lr;
#pragma unroll
        for (int half = 0; half < 2; half++) {
            int m = r0 + half * 8;
#pragma unroll
            for (int nt = 0; nt < NT; nt++) {
                float v0 = acc[mt][nt][half * 2 + 0];
                float v1 = acc[mt][nt][half * 2 + 1];
                int colL = wn * WN + nt * 8 + lc * 2;
                if (MODE == 0) {
                    float* dst = g_t1 + (size_t)m * 384 + n0 + colL;
                    dst[0] = tf32r(gelu_f(v0));
                    dst[1] = tf32r(gelu_f(v1));
                } else if (MODE == 1) {
                    float* dst = g_t2 + (size_t)m * 768 + n0 + colL;
                    *(float2*)dst = make_float2(v0, v1);
                } else {
                    int b = m >> 2, y = m & 3;
                    int n = nw0 + colL, nh = n >> 6, d = n & 63;
                    float* bp = Cout + (size_t)which * OUTSZ
                              + (((size_t)b * 12 + nh) * 20 + y * 5) * 64 + d;
                    float2 v = make_float2(v0, v1);
#pragma unroll
                    for (int xx = 0; xx < 5; xx++) *(float2*)(bp + xx * 64) = v;
                }
            }
        }
    }
}

// ---------------- launch ----------------
extern "C" void kernel_launch(void* const* d_in, const int* in_sizes, int n_in,
                              void* d_out, int out_size) {
    const float* x  = (const float*)d_in[0];
    const float* w1 = (const float*)d_in[1];
    const float* w2 = (const float*)d_in[2];
    const float* wq = (const float*)d_in[3];
    const float* wk = (const float*)d_in[4];
    const float* wv = (const float*)d_in[5];
    float* out = (float*)d_out;

    const int SM128 = 3 * (128 * 36 + 128 * 36) * 4;   // 110592
    const int SM256 = 3 * (128 * 36 + 256 * 36) * 4;   // 165888
    cudaFuncSetAttribute(gemm_mma<0, 128>, cudaFuncAttributeMaxDynamicSharedMemorySize, SM128);
    cudaFuncSetAttribute(gemm_mma<1, 256>, cudaFuncAttributeMaxDynamicSharedMemorySize, SM256);
    cudaFuncSetAttribute(gemm_mma<2, 256>, cudaFuncAttributeMaxDynamicSharedMemorySize, SM256);

    krnd_x<<<(40960 * 192 + 255) / 256, 256>>>(x);
    krnd_w<<<(384 * 192 + 255) / 256, 256>>>(w1, 384 * 192, 0);
    krnd_w<<<(768 * 192 + 255) / 256, 256>>>(wq, 768 * 192, 1);
    krnd_w<<<(768 * 192 + 255) / 256, 256>>>(wk, 768 * 192, 2);
    krnd_w<<<(768 * 192 + 255) / 256, 256>>>(wv, 768 * 192, 3);
    k0_w2t<<<(768 * 3456 + 255) / 256, 256>>>(w2);

    gemm_mma<0, 128><<<dim3(3, 320), 256, SM128>>>(nullptr);  // t1 = gelu(X@W1^T)
    gemm_mma<1, 256><<<dim3(3, 320), 256, SM256>>>(nullptr);  // conv3x3 (implicit im2col)
    kfilter<<<(2048 * 192 + 255) / 256, 256>>>();             // gelu + analytic low-pass
    gemm_mma<2, 256><<<dim3(9, 64), 256, SM256>>>(out);       // QKV + replicated scatter
}

// round 6
// speedup vs baseline: 3.6671x; 1.6072x over previous
#include <cuda_runtime.h>
#include <cuda_fp16.h>
#include <math.h>
#include <stdint.h>

typedef uint32_t u32;

#define OUTSZ (2048u*12u*20u*64u)

// ---------------- static device scratch (fp16 operands everywhere) ----------------
__device__ __align__(256) __half g_xh  [40960u*768u];   // X packed (CLS dropped), fp16
__device__ __align__(256) __half g_w1h [384u*768u];
__device__ __align__(256) __half g_wqh [768u*768u];
__device__ __align__(256) __half g_wkh [768u*768u];
__device__ __align__(256) __half g_wvh [768u*768u];
__device__ __align__(256) __half g_w2th[768u*3456u];    // w2 -> [o][tap*384+i]
__device__ __align__(256) __half g_t1h [40960u*384u];   // gelu(conv1x1)
__device__ __align__(256) __half g_t2h [40960u*768u];   // conv3x3 output
__device__ __align__(256) __half g_fh  [8192u*768u];    // filtered rows

// ---------------- helpers ----------------
__device__ __forceinline__ u32 smem_u32(const void* p) {
    u32 a;
    asm("{ .reg .u64 t; cvta.to.shared.u64 t, %1; cvt.u32.u64 %0, t; }" : "=r"(a) : "l"(p));
    return a;
}
__device__ __forceinline__ float gelu_f(float v) {
    return 0.5f * v * (1.0f + erff(v * 0.7071067811865476f));
}

#define CPA(sa, ga, sz) asm volatile("cp.async.cg.shared.global [%0], [%1], 16, %2;" :: "r"(sa), "l"(ga), "r"(sz) : "memory")
#define CPC()  asm volatile("cp.async.commit_group;" ::: "memory")
#define CPW(n) asm volatile("cp.async.wait_group %0;" :: "n"(n) : "memory")

__device__ __forceinline__ void mma16(float* c, const u32* a, const u32* b) {
    asm volatile("mma.sync.aligned.m16n8k16.row.col.f32.f16.f16.f32 "
        "{%0,%1,%2,%3}, {%4,%5,%6,%7}, {%8,%9}, {%0,%1,%2,%3};"
        : "+f"(c[0]), "+f"(c[1]), "+f"(c[2]), "+f"(c[3])
        : "r"(a[0]), "r"(a[1]), "r"(a[2]), "r"(a[3]), "r"(b[0]), "r"(b[1]));
}

__device__ __forceinline__ uint4 pack8h(float4 a, float4 b) {
    __half2 h0 = __floats2half2_rn(a.x, a.y), h1 = __floats2half2_rn(a.z, a.w);
    __half2 h2 = __floats2half2_rn(b.x, b.y), h3 = __floats2half2_rn(b.z, b.w);
    uint4 u;
    u.x = *(const unsigned*)&h0; u.y = *(const unsigned*)&h1;
    u.z = *(const unsigned*)&h2; u.w = *(const unsigned*)&h3;
    return u;
}

// ---------------- prep kernels: f32 -> fp16 (rn) ----------------
__global__ void kprep_x(const float* __restrict__ X) {
    int idx = blockIdx.x * 256 + threadIdx.x;     // over 40960*96 groups of 8 floats
    if (idx >= 40960 * 96) return;
    int m = idx / 96, c = idx - m * 96;
    const float* src = X + ((size_t)m + m / 20 + 1) * 768 + c * 8;
    float4 a = *(const float4*)src, b = *(const float4*)(src + 4);
    *(uint4*)(g_xh + (size_t)m * 768 + c * 8) = pack8h(a, b);
}
__global__ void kprep_w(const float* __restrict__ src, int n8, int sel) {
    int idx = blockIdx.x * 256 + threadIdx.x;
    if (idx >= n8) return;
    __half* dst = (sel == 0) ? g_w1h : (sel == 1) ? g_wqh : (sel == 2) ? g_wkh : g_wvh;
    float4 a = *(const float4*)(src + (size_t)idx * 8);
    float4 b = *(const float4*)(src + (size_t)idx * 8 + 4);
    *(uint4*)(dst + (size_t)idx * 8) = pack8h(a, b);
}
__global__ void kprep_w2t(const float* __restrict__ w2) {
    int idx = blockIdx.x * 256 + threadIdx.x;     // over 768*3456
    if (idx >= 768 * 3456) return;
    int o = idx / 3456, r = idx - o * 3456;
    int t = r / 384, i = r - t * 384;
    g_w2th[idx] = __float2half(w2[((size_t)o * 384 + i) * 9 + t]);
}

// ---------------- filter: gelu + analytic FFT low-pass (2 surviving freqs) ----------------
__global__ void kfilter() {
    int idx = blockIdx.x * 256 + threadIdx.x;     // over 2048*192 (4 channels each)
    if (idx >= 2048 * 192) return;
    int b = idx / 192, oq = idx - b * 192;
    const __half* src = g_t2h + (size_t)b * (20 * 768) + oq * 4;
    float ry[4][4];
#pragma unroll
    for (int y = 0; y < 4; y++) {
        float a0 = 0.f, a1 = 0.f, a2 = 0.f, a3 = 0.f;
#pragma unroll
        for (int x = 0; x < 5; x++) {
            const __half2* p = (const __half2*)(src + (size_t)(y * 5 + x) * 768);
            float2 v01 = __half22float2(p[0]);
            float2 v23 = __half22float2(p[1]);
            a0 += gelu_f(v01.x); a1 += gelu_f(v01.y);
            a2 += gelu_f(v23.x); a3 += gelu_f(v23.y);
        }
        ry[y][0] = a0; ry[y][1] = a1; ry[y][2] = a2; ry[y][3] = a3;
    }
    __half o[4][4];
#pragma unroll
    for (int j = 0; j < 4; j++) {
        float S  = ry[0][j] + ry[1][j] + ry[2][j] + ry[3][j];
        float A  = ry[0][j] - ry[2][j];
        float Bv = ry[1][j] - ry[3][j];
        o[0][j] = __float2half(sqrtf((S + A) * (S + A) + Bv * Bv) * 0.05f);
        o[1][j] = __float2half(sqrtf((S + Bv) * (S + Bv) + A * A) * 0.05f);
        o[2][j] = __float2half(sqrtf((S - A) * (S - A) + Bv * Bv) * 0.05f);
        o[3][j] = __float2half(sqrtf((S - Bv) * (S - Bv) + A * A) * 0.05f);
    }
    __half* dst = g_fh + (size_t)b * 4 * 768 + oq * 4;
#pragma unroll
    for (int y = 0; y < 4; y++) {
        uint2 u;
        __half2 h0; h0.x = o[y][0]; h0.y = o[y][1];
        __half2 h1; h1.x = o[y][2]; h1.y = o[y][3];
        u.x = *(const unsigned*)&h0; u.y = *(const unsigned*)&h1;
        *(uint2*)(dst + (size_t)y * 768) = u;
    }
}

// ---------------- fp16 mma.sync GEMM ----------------
// MODE 0: g_t1h = fp16(gelu(g_xh @ g_w1h^T))            M=40960 N=384  K=768   BN=128
// MODE 1: g_t2h = im2col(g_t1h) @ g_w2th^T (implicit)   M=40960 N=768  K=3456  BN=256
// MODE 2: out  = g_fh @ {wq|wk|wv}^T, 5x token scatter  M=8192  N=2304 K=768   BN=256
// BM=128, BK=32 (2 x k16), 4-stage cp.async, 8 warps 2(M)x4(N), warp tile 64 x (BN/4)
template<int MODE, int BN>
__global__ __launch_bounds__(256, 1) void gemm_h(float* __restrict__ Cout) {
    constexpr int KTOT = (MODE == 1) ? 3456 : 768;
    constexpr int L = KTOT / 32;
    constexpr int LDSH = 40;                       // halves per smem row (20 words: conflict-free)
    constexpr int ASMH = 128 * LDSH;               // A stage halves
    constexpr int BSMH = BN * LDSH;
    constexpr int STGH = ASMH + BSMH;
    constexpr int NB = BN / 64;                    // B 16B-slots per thread (2 or 4)
    constexpr int WN = BN / 4;
    constexpr int NT = WN / 8;
    constexpr int MT = 4;

    extern __shared__ __half smh[];
    const u32 sbase = smem_u32(smh);
    const int tid = threadIdx.x, wid = tid >> 5, lane = tid & 31;
    const int wm = wid >> 2, wn = wid & 3;
    const int lr = lane >> 2, lc = lane & 3;
    const int n0 = blockIdx.x * BN, m0 = blockIdx.y * 128;

    int which = 0, nw0 = n0;
    const __half* Bb;
    if (MODE == 2) {
        which = n0 / 768; nw0 = n0 - which * 768;
        Bb = (which == 0) ? g_wqh : (which == 1) ? g_wkh : g_wvh;
    } else {
        Bb = (MODE == 0) ? g_w1h : g_w2th;
    }
    const __half* Ab = (MODE == 0) ? g_xh : (MODE == 1) ? g_t1h : g_fh;

    // per-thread cp.async slots: A 2 slots, B NB slots (16B each)
    u32 saoff[2]; const __half* aptr[2];
    int ab20[2], ay[2], ax[2], akf[2];
#pragma unroll
    for (int v = 0; v < 2; v++) {
        int idx = v * 256 + tid, r = idx >> 2, c4 = idx & 3;   // r: 0..127
        saoff[v] = (u32)(r * LDSH + c4 * 8) * 2u;
        if (MODE != 1) {
            aptr[v] = Ab + (size_t)(m0 + r) * KTOT + c4 * 8;
        } else {
            int m = m0 + r, b = m / 20, p = m - b * 20;
            ab20[v] = b * 20; ay[v] = p / 5; ax[v] = p - (p / 5) * 5; akf[v] = c4 * 8;
        }
    }
    u32 sboff[NB]; const __half* bptr[NB];
#pragma unroll
    for (int v = 0; v < NB; v++) {
        int idx = v * 256 + tid, r = idx >> 2, c4 = idx & 3;   // r: 0..BN-1
        sboff[v] = (u32)(ASMH + r * LDSH + c4 * 8) * 2u;
        bptr[v] = Bb + (size_t)(nw0 + r) * KTOT + c4 * 8;
    }

    auto load = [&](int c, int s) {
        u32 base = sbase + (u32)(s * STGH) * 2u;
        if (MODE == 1) {
            int tap = c / 12, kk = (c - tap * 12) * 32;
            int dy = tap / 3 - 1, dx = tap - (tap / 3) * 3 - 1;
#pragma unroll
            for (int v = 0; v < 2; v++) {
                int ny = ay[v] + dy, nx = ax[v] + dx;
                bool ok = ((unsigned)ny < 4u) && ((unsigned)nx < 5u);
                const __half* src = g_t1h + ((size_t)(ab20[v] + ny * 5 + nx) * 384 + kk + akf[v]);
                CPA(base + saoff[v], ok ? src : (const __half*)g_t1h, ok ? 16u : 0u);
            }
        } else {
#pragma unroll
            for (int v = 0; v < 2; v++) CPA(base + saoff[v], aptr[v] + (size_t)c * 32, 16u);
        }
#pragma unroll
        for (int v = 0; v < NB; v++) CPA(base + sboff[v], bptr[v] + (size_t)c * 32, 16u);
        CPC();
    };

    float acc[MT][NT][4];
#pragma unroll
    for (int i = 0; i < MT; i++)
#pragma unroll
        for (int j = 0; j < NT; j++)
#pragma unroll
            for (int q = 0; q < 4; q++) acc[i][j][q] = 0.f;

    load(0, 0);
    load(1, 1);
    load(2, 2);

    for (int c = 0; c < L; c++) {
        int s = c & 3;
        CPW(2);
        __syncthreads();
        if (c + 3 < L) load(c + 3, (c + 3) & 3); else CPC();

        const __half* As = smh + s * STGH;
        const __half* Bs = smh + s * STGH + ASMH;
#pragma unroll
        for (int ks = 0; ks < 2; ks++) {
            u32 af[MT][4];
#pragma unroll
            for (int mt = 0; mt < MT; mt++) {
                int row = wm * 64 + mt * 16 + lr;
                int base = row * LDSH + ks * 16 + lc * 2;
                af[mt][0] = *(const u32*)&As[base];
                af[mt][1] = *(const u32*)&As[base + 8 * LDSH];
                af[mt][2] = *(const u32*)&As[base + 8];
                af[mt][3] = *(const u32*)&As[base + 8 * LDSH + 8];
            }
            u32 bf[NT][2];
#pragma unroll
            for (int nt = 0; nt < NT; nt++) {
                int rn = wn * WN + nt * 8 + lr;
                int base = rn * LDSH + ks * 16 + lc * 2;
                bf[nt][0] = *(const u32*)&Bs[base];
                bf[nt][1] = *(const u32*)&Bs[base + 8];
            }
#pragma unroll
            for (int mt = 0; mt < MT; mt++)
#pragma unroll
                for (int nt = 0; nt < NT; nt++)
                    mma16(acc[mt][nt], af[mt], bf[nt]);
        }
        __syncthreads();
    }

    // ---------------- epilogue ----------------
#pragma unroll
    for (int mt = 0; mt < MT; mt++) {
        int r0 = m0 + wm * 64 + mt * 16 + lr;
#pragma unroll
        for (int half = 0; half < 2; half++) {
            int m = r0 + half * 8;
#pragma unroll
            for (int nt = 0; nt < NT; nt++) {
                float v0 = acc[mt][nt][half * 2 + 0];
                float v1 = acc[mt][nt][half * 2 + 1];
                int colL = wn * WN + nt * 8 + lc * 2;
                if (MODE == 0) {
                    __half2 h = __floats2half2_rn(gelu_f(v0), gelu_f(v1));
                    *(__half2*)(g_t1h + (size_t)m * 384 + n0 + colL) = h;
                } else if (MODE == 1) {
                    __half2 h = __floats2half2_rn(v0, v1);
                    *(__half2*)(g_t2h + (size_t)m * 768 + n0 + colL) = h;
                } else {
                    int b = m >> 2, y = m & 3;
                    int n = nw0 + colL, nh = n >> 6, d = n & 63;
                    float* bp = Cout + (size_t)which * OUTSZ
                              + (((size_t)b * 12 + nh) * 20 + y * 5) * 64 + d;
                    float2 v = make_float2(v0, v1);
#pragma unroll
                    for (int xx = 0; xx < 5; xx++) *(float2*)(bp + xx * 64) = v;
                }
            }
        }
    }
}

// ---------------- launch ----------------
extern "C" void kernel_launch(void* const* d_in, const int* in_sizes, int n_in,
                              void* d_out, int out_size) {
    const float* x  = (const float*)d_in[0];
    const float* w1 = (const float*)d_in[1];
    const float* w2 = (const float*)d_in[2];
    const float* wq = (const float*)d_in[3];
    const float* wk = (const float*)d_in[4];
    const float* wv = (const float*)d_in[5];
    float* out = (float*)d_out;

    const int SM128 = 4 * (128 * 40 + 128 * 40) * 2;   // 81920
    const int SM256 = 4 * (128 * 40 + 256 * 40) * 2;   // 122880
    cudaFuncSetAttribute(gemm_h<0, 128>, cudaFuncAttributeMaxDynamicSharedMemorySize, SM128);
    cudaFuncSetAttribute(gemm_h<1, 256>, cudaFuncAttributeMaxDynamicSharedMemorySize, SM256);
    cudaFuncSetAttribute(gemm_h<2, 256>, cudaFuncAttributeMaxDynamicSharedMemorySize, SM256);

    kprep_x<<<(40960 * 96 + 255) / 256, 256>>>(x);
    kprep_w<<<(384 * 96 + 255) / 256, 256>>>(w1, 384 * 96, 0);
    kprep_w<<<(768 * 96 + 255) / 256, 256>>>(wq, 768 * 96, 1);
    kprep_w<<<(768 * 96 + 255) / 256, 256>>>(wk, 768 * 96, 2);
    kprep_w<<<(768 * 96 + 255) / 256, 256>>>(wv, 768 * 96, 3);
    kprep_w2t<<<(768 * 3456 + 255) / 256, 256>>>(w2);

    gemm_h<0, 128><<<dim3(3, 320), 256, SM128>>>(nullptr);  // t1 = gelu(X@W1^T)
    gemm_h<1, 256><<<dim3(3, 320), 256, SM256>>>(nullptr);  // conv3x3 (implicit im2col)
    kfilter<<<(2048 * 192 + 255) / 256, 256>>>();           // gelu + analytic low-pass
    gemm_h<2, 256><<<dim3(9, 64), 256, SM256>>>(out);       // QKV + replicated scatter
}

// round 7
// speedup vs baseline: 3.8482x; 1.0494x over previous
#include <cuda_runtime.h>
#include <cuda_fp16.h>
#include <math.h>
#include <stdint.h>

typedef uint32_t u32;

#define OUTSZ (2048u*12u*20u*64u)

// ---------------- static device scratch (fp16 operands everywhere) ----------------
__device__ __align__(256) __half g_xh  [40960u*768u];   // X packed (CLS dropped), fp16
__device__ __align__(256) __half g_w1h [384u*768u];
__device__ __align__(256) __half g_wqh [768u*768u];
__device__ __align__(256) __half g_wkh [768u*768u];
__device__ __align__(256) __half g_wvh [768u*768u];
__device__ __align__(256) __half g_w2th[768u*3456u];    // w2 -> [o][tap*384+i]
__device__ __align__(256) __half g_t1h [40960u*384u];   // gelu(conv1x1)
__device__ __align__(256) __half g_t2h [40960u*768u];   // conv3x3 output
__device__ __align__(256) __half g_fh  [8192u*768u];    // filtered rows

// ---------------- helpers ----------------
__device__ __forceinline__ u32 smem_u32(const void* p) {
    u32 a;
    asm("{ .reg .u64 t; cvta.to.shared.u64 t, %1; cvt.u32.u64 %0, t; }" : "=r"(a) : "l"(p));
    return a;
}
__device__ __forceinline__ float gelu_f(float v) {
    return 0.5f * v * (1.0f + erff(v * 0.7071067811865476f));
}

#define CPA(sa, ga, sz) asm volatile("cp.async.cg.shared.global [%0], [%1], 16, %2;" :: "r"(sa), "l"(ga), "r"(sz) : "memory")
#define CPC()  asm volatile("cp.async.commit_group;" ::: "memory")
#define CPW(n) asm volatile("cp.async.wait_group %0;" :: "n"(n) : "memory")

__device__ __forceinline__ void mma16(float* c, const u32* a, const u32* b) {
    asm volatile("mma.sync.aligned.m16n8k16.row.col.f32.f16.f16.f32 "
        "{%0,%1,%2,%3}, {%4,%5,%6,%7}, {%8,%9}, {%0,%1,%2,%3};"
        : "+f"(c[0]), "+f"(c[1]), "+f"(c[2]), "+f"(c[3])
        : "r"(a[0]), "r"(a[1]), "r"(a[2]), "r"(a[3]), "r"(b[0]), "r"(b[1]));
}
__device__ __forceinline__ void ldmx4(u32& r0, u32& r1, u32& r2, u32& r3, u32 addr) {
    asm volatile("ldmatrix.sync.aligned.m8n8.x4.shared.b16 {%0,%1,%2,%3}, [%4];"
                 : "=r"(r0), "=r"(r1), "=r"(r2), "=r"(r3) : "r"(addr));
}

__device__ __forceinline__ uint4 pack8h(float4 a, float4 b) {
    __half2 h0 = __floats2half2_rn(a.x, a.y), h1 = __floats2half2_rn(a.z, a.w);
    __half2 h2 = __floats2half2_rn(b.x, b.y), h3 = __floats2half2_rn(b.z, b.w);
    uint4 u;
    u.x = *(const unsigned*)&h0; u.y = *(const unsigned*)&h1;
    u.z = *(const unsigned*)&h2; u.w = *(const unsigned*)&h3;
    return u;
}

// ---------------- prep kernels: f32 -> fp16 (rn) ----------------
__global__ void kprep_x(const float* __restrict__ X) {
    int idx = blockIdx.x * 256 + threadIdx.x;     // over 40960*96 groups of 8 floats
    if (idx >= 40960 * 96) return;
    int m = idx / 96, c = idx - m * 96;
    const float* src = X + ((size_t)m + m / 20 + 1) * 768 + c * 8;
    float4 a = *(const float4*)src, b = *(const float4*)(src + 4);
    *(uint4*)(g_xh + (size_t)m * 768 + c * 8) = pack8h(a, b);
}
__global__ void kprep_w(const float* __restrict__ src, int n8, int sel) {
    int idx = blockIdx.x * 256 + threadIdx.x;
    if (idx >= n8) return;
    __half* dst = (sel == 0) ? g_w1h : (sel == 1) ? g_wqh : (sel == 2) ? g_wkh : g_wvh;
    float4 a = *(const float4*)(src + (size_t)idx * 8);
    float4 b = *(const float4*)(src + (size_t)idx * 8 + 4);
    *(uint4*)(dst + (size_t)idx * 8) = pack8h(a, b);
}
__global__ void kprep_w2t(const float* __restrict__ w2) {
    int idx = blockIdx.x * 256 + threadIdx.x;     // over 768*3456
    if (idx >= 768 * 3456) return;
    int o = idx / 3456, r = idx - o * 3456;
    int t = r / 384, i = r - t * 384;
    g_w2th[idx] = __float2half(w2[((size_t)o * 384 + i) * 9 + t]);
}

// ---------------- filter: gelu + analytic FFT low-pass (2 surviving freqs) ----------------
__global__ void kfilter() {
    int idx = blockIdx.x * 256 + threadIdx.x;     // over 2048*192 (4 channels each)
    if (idx >= 2048 * 192) return;
    int b = idx / 192, oq = idx - b * 192;
    const __half* src = g_t2h + (size_t)b * (20 * 768) + oq * 4;
    float ry[4][4];
#pragma unroll
    for (int y = 0; y < 4; y++) {
        float a0 = 0.f, a1 = 0.f, a2 = 0.f, a3 = 0.f;
#pragma unroll
        for (int x = 0; x < 5; x++) {
            const __half2* p = (const __half2*)(src + (size_t)(y * 5 + x) * 768);
            float2 v01 = __half22float2(p[0]);
            float2 v23 = __half22float2(p[1]);
            a0 += gelu_f(v01.x); a1 += gelu_f(v01.y);
            a2 += gelu_f(v23.x); a3 += gelu_f(v23.y);
        }
        ry[y][0] = a0; ry[y][1] = a1; ry[y][2] = a2; ry[y][3] = a3;
    }
    __half o[4][4];
#pragma unroll
    for (int j = 0; j < 4; j++) {
        float S  = ry[0][j] + ry[1][j] + ry[2][j] + ry[3][j];
        float A  = ry[0][j] - ry[2][j];
        float Bv = ry[1][j] - ry[3][j];
        o[0][j] = __float2half(sqrtf((S + A) * (S + A) + Bv * Bv) * 0.05f);
        o[1][j] = __float2half(sqrtf((S + Bv) * (S + Bv) + A * A) * 0.05f);
        o[2][j] = __float2half(sqrtf((S - A) * (S - A) + Bv * Bv) * 0.05f);
        o[3][j] = __float2half(sqrtf((S - Bv) * (S - Bv) + A * A) * 0.05f);
    }
    __half* dst = g_fh + (size_t)b * 4 * 768 + oq * 4;
#pragma unroll
    for (int y = 0; y < 4; y++) {
        uint2 u;
        __half2 h0; h0.x = o[y][0]; h0.y = o[y][1];
        __half2 h1; h1.x = o[y][2]; h1.y = o[y][3];
        u.x = *(const unsigned*)&h0; u.y = *(const unsigned*)&h1;
        *(uint2*)(dst + (size_t)y * 768) = u;
    }
}

// ---------------- fp16 mma.sync GEMM (ldmatrix fragment loads) ----------------
// MODE 0: g_t1h = fp16(gelu(g_xh @ g_w1h^T))            M=40960 N=384  K=768   BN=128
// MODE 1: g_t2h = im2col(g_t1h) @ g_w2th^T (implicit)   M=40960 N=768  K=3456  BN=256
// MODE 2: out  = g_fh @ {wq|wk|wv}^T, 5x token scatter  M=8192  N=2304 K=768   BN=256
// BM=128, BK=32 (2 x k16), 4-stage cp.async, 8 warps 2(M)x4(N), warp tile 64 x (BN/4)
template<int MODE, int BN>
__global__ __launch_bounds__(256, 1) void gemm_h(float* __restrict__ Cout) {
    constexpr int KTOT = (MODE == 1) ? 3456 : 768;
    constexpr int L = KTOT / 32;
    constexpr int LDSH = 40;                       // halves per smem row (conflict-free for ldmatrix)
    constexpr int ASMH = 128 * LDSH;
    constexpr int BSMH = BN * LDSH;
    constexpr int STGH = ASMH + BSMH;
    constexpr int NB = BN / 64;
    constexpr int WN = BN / 4;
    constexpr int NT = WN / 8;
    constexpr int MT = 4;
    constexpr int NTP = NT / 2;                    // B ldmatrix.x4 groups per ks

    extern __shared__ __half smh[];
    const u32 sbase = smem_u32(smh);
    const int tid = threadIdx.x, wid = tid >> 5, lane = tid & 31;
    const int wm = wid >> 2, wn = wid & 3;
    const int lr = lane >> 2, lc = lane & 3;
    const int n0 = blockIdx.x * BN, m0 = blockIdx.y * 128;

    int which = 0, nw0 = n0;
    const __half* Bb;
    if (MODE == 2) {
        which = n0 / 768; nw0 = n0 - which * 768;
        Bb = (which == 0) ? g_wqh : (which == 1) ? g_wkh : g_wvh;
    } else {
        Bb = (MODE == 0) ? g_w1h : g_w2th;
    }
    const __half* Ab = (MODE == 0) ? g_xh : (MODE == 1) ? g_t1h : g_fh;

    // ldmatrix per-thread base offsets (halves)
    // A x4: matrix i (i=lane>>3): rows (i&1)*8, cols (i>>1)*8
    const int arow_t = wm * 64 + ((lane >> 3) & 1) * 8 + (lane & 7);
    const int acol_t = (lane >> 4) * 8;
    // B x4: matrix i: nt-sub (i>>1)*8 rows, khalf (i&1)*8 cols
    const int brow_t = wn * WN + (lane >> 4) * 8 + (lane & 7);
    const int bcol_t = ((lane >> 3) & 1) * 8;

    // per-thread cp.async slots: A 2 slots, B NB slots (16B each)
    u32 saoff[2]; const __half* aptr[2];
    int ab20[2], ay[2], ax[2], akf[2];
#pragma unroll
    for (int v = 0; v < 2; v++) {
        int idx = v * 256 + tid, r = idx >> 2, c4 = idx & 3;   // r: 0..127
        saoff[v] = (u32)(r * LDSH + c4 * 8) * 2u;
        if (MODE != 1) {
            aptr[v] = Ab + (size_t)(m0 + r) * KTOT + c4 * 8;
        } else {
            int m = m0 + r, b = m / 20, p = m - b * 20;
            ab20[v] = b * 20; ay[v] = p / 5; ax[v] = p - (p / 5) * 5; akf[v] = c4 * 8;
        }
    }
    u32 sboff[NB]; const __half* bptr[NB];
#pragma unroll
    for (int v = 0; v < NB; v++) {
        int idx = v * 256 + tid, r = idx >> 2, c4 = idx & 3;   // r: 0..BN-1
        sboff[v] = (u32)(ASMH + r * LDSH + c4 * 8) * 2u;
        bptr[v] = Bb + (size_t)(nw0 + r) * KTOT + c4 * 8;
    }

    auto load = [&](int c, int s) {
        u32 base = sbase + (u32)(s * STGH) * 2u;
        if (MODE == 1) {
            int tap = c / 12, kk = (c - tap * 12) * 32;
            int dy = tap / 3 - 1, dx = tap - (tap / 3) * 3 - 1;
#pragma unroll
            for (int v = 0; v < 2; v++) {
                int ny = ay[v] + dy, nx = ax[v] + dx;
                bool ok = ((unsigned)ny < 4u) && ((unsigned)nx < 5u);
                const __half* src = g_t1h + ((size_t)(ab20[v] + ny * 5 + nx) * 384 + kk + akf[v]);
                CPA(base + saoff[v], ok ? src : (const __half*)g_t1h, ok ? 16u : 0u);
            }
        } else {
#pragma unroll
            for (int v = 0; v < 2; v++) CPA(base + saoff[v], aptr[v] + (size_t)c * 32, 16u);
        }
#pragma unroll
        for (int v = 0; v < NB; v++) CPA(base + sboff[v], bptr[v] + (size_t)c * 32, 16u);
        CPC();
    };

    float acc[MT][NT][4];
#pragma unroll
    for (int i = 0; i < MT; i++)
#pragma unroll
        for (int j = 0; j < NT; j++)
#pragma unroll
            for (int q = 0; q < 4; q++) acc[i][j][q] = 0.f;

    load(0, 0);
    load(1, 1);
    load(2, 2);

    for (int c = 0; c < L; c++) {
        int s = c & 3;
        CPW(2);
        __syncthreads();
        if (c + 3 < L) load(c + 3, (c + 3) & 3); else CPC();

        const u32 sA = sbase + (u32)(s * STGH) * 2u;
        const u32 sB = sA + (u32)ASMH * 2u;
#pragma unroll
        for (int ks = 0; ks < 2; ks++) {
            u32 af[MT][4];
#pragma unroll
            for (int mt = 0; mt < MT; mt++) {
                u32 addr = sA + (u32)((arow_t + mt * 16) * LDSH + acol_t + ks * 16) * 2u;
                ldmx4(af[mt][0], af[mt][1], af[mt][2], af[mt][3], addr);
            }
            u32 bf[NT][2];
#pragma unroll
            for (int np = 0; np < NTP; np++) {
                u32 addr = sB + (u32)((brow_t + np * 16) * LDSH + bcol_t + ks * 16) * 2u;
                ldmx4(bf[np * 2][0], bf[np * 2][1], bf[np * 2 + 1][0], bf[np * 2 + 1][1], addr);
            }
#pragma unroll
            for (int mt = 0; mt < MT; mt++)
#pragma unroll
                for (int nt = 0; nt < NT; nt++)
                    mma16(acc[mt][nt], af[mt], bf[nt]);
        }
        __syncthreads();
    }

    // ---------------- epilogue ----------------
#pragma unroll
    for (int mt = 0; mt < MT; mt++) {
        int r0 = m0 + wm * 64 + mt * 16 + lr;
#pragma unroll
        for (int half = 0; half < 2; half++) {
            int m = r0 + half * 8;
#pragma unroll
            for (int nt = 0; nt < NT; nt++) {
                float v0 = acc[mt][nt][half * 2 + 0];
                float v1 = acc[mt][nt][half * 2 + 1];
                int colL = wn * WN + nt * 8 + lc * 2;
                if (MODE == 0) {
                    __half2 h = __floats2half2_rn(gelu_f(v0), gelu_f(v1));
                    *(__half2*)(g_t1h + (size_t)m * 384 + n0 + colL) = h;
                } else if (MODE == 1) {
                    __half2 h = __floats2half2_rn(v0, v1);
                    *(__half2*)(g_t2h + (size_t)m * 768 + n0 + colL) = h;
                } else {
                    int b = m >> 2, y = m & 3;
                    int n = nw0 + colL, nh = n >> 6, d = n & 63;
                    float* bp = Cout + (size_t)which * OUTSZ
                              + (((size_t)b * 12 + nh) * 20 + y * 5) * 64 + d;
                    float2 v = make_float2(v0, v1);
#pragma unroll
                    for (int xx = 0; xx < 5; xx++) *(float2*)(bp + xx * 64) = v;
                }
            }
        }
    }
}

// ---------------- launch ----------------
extern "C" void kernel_launch(void* const* d_in, const int* in_sizes, int n_in,
                              void* d_out, int out_size) {
    const float* x  = (const float*)d_in[0];
    const float* w1 = (const float*)d_in[1];
    const float* w2 = (const float*)d_in[2];
    const float* wq = (const float*)d_in[3];
    const float* wk = (const float*)d_in[4];
    const float* wv = (const float*)d_in[5];
    float* out = (float*)d_out;

    const int SM128 = 4 * (128 * 40 + 128 * 40) * 2;   // 81920
    const int SM256 = 4 * (128 * 40 + 256 * 40) * 2;   // 122880
    cudaFuncSetAttribute(gemm_h<0, 128>, cudaFuncAttributeMaxDynamicSharedMemorySize, SM128);
    cudaFuncSetAttribute(gemm_h<1, 256>, cudaFuncAttributeMaxDynamicSharedMemorySize, SM256);
    cudaFuncSetAttribute(gemm_h<2, 256>, cudaFuncAttributeMaxDynamicSharedMemorySize, SM256);

    kprep_x<<<(40960 * 96 + 255) / 256, 256>>>(x);
    kprep_w<<<(384 * 96 + 255) / 256, 256>>>(w1, 384 * 96, 0);
    kprep_w<<<(768 * 96 + 255) / 256, 256>>>(wq, 768 * 96, 1);
    kprep_w<<<(768 * 96 + 255) / 256, 256>>>(wk, 768 * 96, 2);
    kprep_w<<<(768 * 96 + 255) / 256, 256>>>(wv, 768 * 96, 3);
    kprep_w2t<<<(768 * 3456 + 255) / 256, 256>>>(w2);

    gemm_h<0, 128><<<dim3(3, 320), 256, SM128>>>(nullptr);  // t1 = gelu(X@W1^T)
    gemm_h<1, 256><<<dim3(3, 320), 256, SM256>>>(nullptr);  // conv3x3 (implicit im2col)
    kfilter<<<(2048 * 192 + 255) / 256, 256>>>();           // gelu + analytic low-pass
    gemm_h<2, 256><<<dim3(9, 64), 256, SM256>>>(out);       // QKV + replicated scatter
}

// round 8
// speedup vs baseline: 5.3328x; 1.3858x over previous
#include <cuda_runtime.h>
#include <cuda_fp16.h>
#include <math.h>
#include <stdint.h>

typedef uint32_t u32;

#define OUTSZ (2048u*12u*20u*64u)

// ---------------- static device scratch (fp16, position-major m' = p*2048 + b) ----------------
__device__ __align__(256) __half g_xh  [40960u*768u];   // X reordered [p][b][768]
__device__ __align__(256) __half g_w1h [384u*768u];
__device__ __align__(256) __half g_wqh [768u*768u];
__device__ __align__(256) __half g_wkh [768u*768u];
__device__ __align__(256) __half g_wvh [768u*768u];
__device__ __align__(256) __half g_w2th[768u*3456u];    // w2 -> [o][tap*384+i]
__device__ __align__(256) __half g_t1h [40960u*384u];   // gelu(conv1x1), [p][b][384]
__device__ __align__(256) __half g_t2h [40960u*768u];   // conv3x3 out, [p][b][768]
__device__ __align__(256) __half g_fh  [8192u*768u];    // filtered rows, [b*4+y][768]

// ---------------- helpers ----------------
__device__ __forceinline__ u32 smem_u32(const void* p) {
    u32 a;
    asm("{ .reg .u64 t; cvta.to.shared.u64 t, %1; cvt.u32.u64 %0, t; }" : "=r"(a) : "l"(p));
    return a;
}
__device__ __forceinline__ float gelu_f(float v) {
    return 0.5f * v * (1.0f + erff(v * 0.7071067811865476f));
}

#define CPA(sa, ga, sz) asm volatile("cp.async.cg.shared.global [%0], [%1], 16, %2;" :: "r"(sa), "l"(ga), "r"(sz) : "memory")
#define CPC()  asm volatile("cp.async.commit_group;" ::: "memory")
#define CPW(n) asm volatile("cp.async.wait_group %0;" :: "n"(n) : "memory")

__device__ __forceinline__ void mma16(float* c, const u32* a, const u32* b) {
    asm volatile("mma.sync.aligned.m16n8k16.row.col.f32.f16.f16.f32 "
        "{%0,%1,%2,%3}, {%4,%5,%6,%7}, {%8,%9}, {%0,%1,%2,%3};"
        : "+f"(c[0]), "+f"(c[1]), "+f"(c[2]), "+f"(c[3])
        : "r"(a[0]), "r"(a[1]), "r"(a[2]), "r"(a[3]), "r"(b[0]), "r"(b[1]));
}
__device__ __forceinline__ void ldmx4(u32& r0, u32& r1, u32& r2, u32& r3, u32 addr) {
    asm volatile("ldmatrix.sync.aligned.m8n8.x4.shared.b16 {%0,%1,%2,%3}, [%4];"
                 : "=r"(r0), "=r"(r1), "=r"(r2), "=r"(r3) : "r"(addr));
}
__device__ __forceinline__ uint4 pack8h(float4 a, float4 b) {
    __half2 h0 = __floats2half2_rn(a.x, a.y), h1 = __floats2half2_rn(a.z, a.w);
    __half2 h2 = __floats2half2_rn(b.x, b.y), h3 = __floats2half2_rn(b.z, b.w);
    uint4 u;
    u.x = *(const unsigned*)&h0; u.y = *(const unsigned*)&h1;
    u.z = *(const unsigned*)&h2; u.w = *(const unsigned*)&h3;
    return u;
}

// ---------------- prep ----------------
__global__ void kprep_x(const float* __restrict__ X) {
    int idx = blockIdx.x * 256 + threadIdx.x;     // over 40960*96 groups of 8 floats
    if (idx >= 40960 * 96) return;
    int mp = idx / 96, c = idx - mp * 96;
    int p = mp >> 11, b = mp & 2047;              // m' = p*2048 + b
    const float* src = X + ((size_t)b * 21 + 1 + p) * 768 + c * 8;
    float4 a = *(const float4*)src, bb = *(const float4*)(src + 4);
    *(uint4*)(g_xh + (size_t)mp * 768 + c * 8) = pack8h(a, bb);
}
__global__ void kprep_w(const float* __restrict__ src, int n8, int sel) {
    int idx = blockIdx.x * 256 + threadIdx.x;
    if (idx >= n8) return;
    __half* dst = (sel == 0) ? g_w1h : (sel == 1) ? g_wqh : (sel == 2) ? g_wkh : g_wvh;
    float4 a = *(const float4*)(src + (size_t)idx * 8);
    float4 b = *(const float4*)(src + (size_t)idx * 8 + 4);
    *(uint4*)(dst + (size_t)idx * 8) = pack8h(a, b);
}
__global__ void kprep_w2t(const float* __restrict__ w2) {
    int idx = blockIdx.x * 256 + threadIdx.x;     // over 768*3456
    if (idx >= 768 * 3456) return;
    int o = idx / 3456, r = idx - o * 3456;
    int t = r / 384, i = r - t * 384;
    g_w2th[idx] = __float2half(w2[((size_t)o * 384 + i) * 9 + t]);
}

// ---------------- filter: gelu + analytic FFT low-pass ----------------
__global__ void kfilter() {
    int idx = blockIdx.x * 256 + threadIdx.x;     // over 2048*192 (4 channels each)
    if (idx >= 2048 * 192) return;
    int b = idx / 192, oq = idx - b * 192;
    const __half* src = g_t2h + (size_t)b * 768 + oq * 4;   // + p*2048*768 per position
    float ry[4][4];
#pragma unroll
    for (int y = 0; y < 4; y++) {
        float a0 = 0.f, a1 = 0.f, a2 = 0.f, a3 = 0.f;
#pragma unroll
        for (int x = 0; x < 5; x++) {
            const __half2* pp = (const __half2*)(src + (size_t)(y * 5 + x) * 2048u * 768u);
            float2 v01 = __half22float2(pp[0]);
            float2 v23 = __half22float2(pp[1]);
            a0 += gelu_f(v01.x); a1 += gelu_f(v01.y);
            a2 += gelu_f(v23.x); a3 += gelu_f(v23.y);
        }
        ry[y][0] = a0; ry[y][1] = a1; ry[y][2] = a2; ry[y][3] = a3;
    }
    __half o[4][4];
#pragma unroll
    for (int j = 0; j < 4; j++) {
        float S  = ry[0][j] + ry[1][j] + ry[2][j] + ry[3][j];
        float A  = ry[0][j] - ry[2][j];
        float Bv = ry[1][j] - ry[3][j];
        o[0][j] = __float2half(sqrtf((S + A) * (S + A) + Bv * Bv) * 0.05f);
        o[1][j] = __float2half(sqrtf((S + Bv) * (S + Bv) + A * A) * 0.05f);
        o[2][j] = __float2half(sqrtf((S - A) * (S - A) + Bv * Bv) * 0.05f);
        o[3][j] = __float2half(sqrtf((S - Bv) * (S - Bv) + A * A) * 0.05f);
    }
    __half* dst = g_fh + (size_t)b * 4 * 768 + oq * 4;
#pragma unroll
    for (int y = 0; y < 4; y++) {
        uint2 u;
        __half2 h0; h0.x = o[y][0]; h0.y = o[y][1];
        __half2 h1; h1.x = o[y][2]; h1.y = o[y][3];
        u.x = *(const unsigned*)&h0; u.y = *(const unsigned*)&h1;
        *(uint2*)(dst + (size_t)y * 768) = u;
    }
}

// =====================================================================
// common GEMM geometry: BM=128, BN=128, BK=32, 3-stage cp.async, 8 warps
// warp tile 64x32 (MT=4, NT=4), ldmatrix fragments, 2 CTAs/SM
// =====================================================================
#define LDSH 40
#define ASMH (128 * LDSH)
#define STGH (2 * ASMH)
#define SMEMB (3 * STGH * 2)

// ---------------- generic GEMM (MODE 0: G1, MODE 2: QKV) ----------------
template<int MODE>
__global__ __launch_bounds__(256, 2) void gemm_h(float* __restrict__ Cout) {
    constexpr int L = 24;                          // 768/32
    extern __shared__ __half smh[];
    const u32 sbase = smem_u32(smh);
    const int tid = threadIdx.x, wid = tid >> 5, lane = tid & 31;
    const int wm = wid >> 2, wn = wid & 3;
    const int lr = lane >> 2, lc = lane & 3;
    const int n0 = blockIdx.x * 128, m0 = blockIdx.y * 128;

    int which = 0, nw0 = n0;
    const __half* Bb;
    if (MODE == 2) {
        which = n0 / 768; nw0 = n0 - which * 768;
        Bb = (which == 0) ? g_wqh : (which == 1) ? g_wkh : g_wvh;
    } else {
        Bb = g_w1h;
    }
    const __half* Ab = (MODE == 0) ? g_xh : g_fh;

    const int arow_t = wm * 64 + ((lane >> 3) & 1) * 8 + (lane & 7);
    const int acol_t = (lane >> 4) * 8;
    const int brow_t = wn * 32 + (lane >> 4) * 8 + (lane & 7);
    const int bcol_t = ((lane >> 3) & 1) * 8;

    u32 saoff[2]; const __half* aptr[2];
    u32 sboff[2]; const __half* bptr[2];
#pragma unroll
    for (int v = 0; v < 2; v++) {
        int idx = v * 256 + tid, r = idx >> 2, c4 = idx & 3;
        saoff[v] = (u32)(r * LDSH + c4 * 8) * 2u;
        aptr[v] = Ab + (size_t)(m0 + r) * 768 + c4 * 8;
        sboff[v] = (u32)(ASMH + r * LDSH + c4 * 8) * 2u;
        bptr[v] = Bb + (size_t)(nw0 + r) * 768 + c4 * 8;
    }

    auto load = [&](int c, int s) {
        u32 base = sbase + (u32)(s * STGH) * 2u;
#pragma unroll
        for (int v = 0; v < 2; v++) CPA(base + saoff[v], aptr[v] + (size_t)c * 32, 16u);
#pragma unroll
        for (int v = 0; v < 2; v++) CPA(base + sboff[v], bptr[v] + (size_t)c * 32, 16u);
        CPC();
    };

    float acc[4][4][4];
#pragma unroll
    for (int i = 0; i < 4; i++)
#pragma unroll
        for (int j = 0; j < 4; j++)
#pragma unroll
            for (int q = 0; q < 4; q++) acc[i][j][q] = 0.f;

    load(0, 0);
    load(1, 1);

    for (int c = 0; c < L; c++) {
        int s = c % 3;
        CPW(1);
        __syncthreads();
        if (c + 2 < L) load(c + 2, (c + 2) % 3); else CPC();

        const u32 sA = sbase + (u32)(s * STGH) * 2u;
        const u32 sB = sA + (u32)ASMH * 2u;
#pragma unroll
        for (int ks = 0; ks < 2; ks++) {
            u32 af[4][4];
#pragma unroll
            for (int mt = 0; mt < 4; mt++) {
                u32 addr = sA + (u32)((arow_t + mt * 16) * LDSH + acol_t + ks * 16) * 2u;
                ldmx4(af[mt][0], af[mt][1], af[mt][2], af[mt][3], addr);
            }
            u32 bf[4][2];
#pragma unroll
            for (int np = 0; np < 2; np++) {
                u32 addr = sB + (u32)((brow_t + np * 16) * LDSH + bcol_t + ks * 16) * 2u;
                ldmx4(bf[np * 2][0], bf[np * 2][1], bf[np * 2 + 1][0], bf[np * 2 + 1][1], addr);
            }
#pragma unroll
            for (int mt = 0; mt < 4; mt++)
#pragma unroll
                for (int nt = 0; nt < 4; nt++)
                    mma16(acc[mt][nt], af[mt], bf[nt]);
        }
        __syncthreads();
    }

#pragma unroll
    for (int mt = 0; mt < 4; mt++) {
        int r0 = m0 + wm * 64 + mt * 16 + lr;
#pragma unroll
        for (int half = 0; half < 2; half++) {
            int m = r0 + half * 8;
#pragma unroll
            for (int nt = 0; nt < 4; nt++) {
                float v0 = acc[mt][nt][half * 2 + 0];
                float v1 = acc[mt][nt][half * 2 + 1];
                int colL = wn * 32 + nt * 8 + lc * 2;
                if (MODE == 0) {
                    __half2 h = __floats2half2_rn(gelu_f(v0), gelu_f(v1));
                    *(__half2*)(g_t1h + (size_t)m * 384 + n0 + colL) = h;
                } else {
                    int b = m >> 2, y = m & 3;
                    int n = nw0 + colL, nh = n >> 6, d = n & 63;
                    float* bp = Cout + (size_t)which * OUTSZ
                              + (((size_t)b * 12 + nh) * 20 + y * 5) * 64 + d;
                    float2 v = make_float2(v0, v1);
#pragma unroll
                    for (int xx = 0; xx < 5; xx++) *(float2*)(bp + xx * 64) = v;
                }
            }
        }
    }
}

// ---------------- conv GEMM: per-CTA single position, valid taps only ----------------
__global__ __launch_bounds__(256, 2) void gemm_conv() {
    extern __shared__ __half smh[];
    const u32 sbase = smem_u32(smh);
    const int tid = threadIdx.x, wid = tid >> 5, lane = tid & 31;
    const int wm = wid >> 2, wn = wid & 3;
    const int lr = lane >> 2, lc = lane & 3;
    const int n0 = blockIdx.x * 128, m0 = blockIdx.y * 128;
    const int p = m0 >> 11;                        // position of this whole tile
    const int py = p / 5, px = p - py * 5;

    // valid tap lists
    int tap_src[9], tap_w[9], ntap = 0;
#pragma unroll
    for (int dy = -1; dy <= 1; dy++) {
        int ny = py + dy; if ((unsigned)ny >= 4u) continue;
#pragma unroll
        for (int dx = -1; dx <= 1; dx++) {
            int nx = px + dx; if ((unsigned)nx >= 5u) continue;
            tap_src[ntap] = ny * 5 + nx;
            tap_w[ntap]   = (dy + 1) * 3 + (dx + 1);
            ntap++;
        }
    }
    const int L = ntap * 12;

    const int arow_t = wm * 64 + ((lane >> 3) & 1) * 8 + (lane & 7);
    const int acol_t = (lane >> 4) * 8;
    const int brow_t = wn * 32 + (lane >> 4) * 8 + (lane & 7);
    const int bcol_t = ((lane >> 3) & 1) * 8;

    u32 saoff[2]; size_t aoff[2];
    u32 sboff[2]; const __half* bptr[2];
#pragma unroll
    for (int v = 0; v < 2; v++) {
        int idx = v * 256 + tid, r = idx >> 2, c4 = idx & 3;
        saoff[v] = (u32)(r * LDSH + c4 * 8) * 2u;
        aoff[v] = (size_t)(m0 + r - p * 2048) * 384 + c4 * 8;   // b-row offset within a position slab
        sboff[v] = (u32)(ASMH + r * LDSH + c4 * 8) * 2u;
        bptr[v] = g_w2th + (size_t)(n0 + r) * 3456 + c4 * 8;
    }

    auto load = [&](int c, int s) {
        int ti = c / 12, kk = (c - ti * 12) * 32;
        const __half* Asl = g_t1h + (size_t)tap_src[ti] * 2048u * 384u + kk;
        const __half* Bsl = g_w2th;   // base in bptr
        int boff = tap_w[ti] * 384 + kk;
        u32 base = sbase + (u32)(s * STGH) * 2u;
#pragma unroll
        for (int v = 0; v < 2; v++) CPA(base + saoff[v], Asl + aoff[v], 16u);
#pragma unroll
        for (int v = 0; v < 2; v++) CPA(base + sboff[v], bptr[v] + boff, 16u);
        (void)Bsl;
        CPC();
    };

    float acc[4][4][4];
#pragma unroll
    for (int i = 0; i < 4; i++)
#pragma unroll
        for (int j = 0; j < 4; j++)
#pragma unroll
            for (int q = 0; q < 4; q++) acc[i][j][q] = 0.f;

    load(0, 0);
    load(1, 1);

    for (int c = 0; c < L; c++) {
        int s = c % 3;
        CPW(1);
        __syncthreads();
        if (c + 2 < L) load(c + 2, (c + 2) % 3); else CPC();

        const u32 sA = sbase + (u32)(s * STGH) * 2u;
        const u32 sB = sA + (u32)ASMH * 2u;
#pragma unroll
        for (int ks = 0; ks < 2; ks++) {
            u32 af[4][4];
#pragma unroll
            for (int mt = 0; mt < 4; mt++) {
                u32 addr = sA + (u32)((arow_t + mt * 16) * LDSH + acol_t + ks * 16) * 2u;
                ldmx4(af[mt][0], af[mt][1], af[mt][2], af[mt][3], addr);
            }
            u32 bf[4][2];
#pragma unroll
            for (int np = 0; np < 2; np++) {
                u32 addr = sB + (u32)((brow_t + np * 16) * LDSH + bcol_t + ks * 16) * 2u;
                ldmx4(bf[np * 2][0], bf[np * 2][1], bf[np * 2 + 1][0], bf[np * 2 + 1][1], addr);
            }
#pragma unroll
            for (int mt = 0; mt < 4; mt++)
#pragma unroll
                for (int nt = 0; nt < 4; nt++)
                    mma16(acc[mt][nt], af[mt], bf[nt]);
        }
        __syncthreads();
    }

#pragma unroll
    for (int mt = 0; mt < 4; mt++) {
        int r0 = m0 + wm * 64 + mt * 16 + lr;
#pragma unroll
        for (int half = 0; half < 2; half++) {
            int m = r0 + half * 8;
#pragma unroll
            for (int nt = 0; nt < 4; nt++) {
                float v0 = acc[mt][nt][half * 2 + 0];
                float v1 = acc[mt][nt][half * 2 + 1];
                int colL = wn * 32 + nt * 8 + lc * 2;
                __half2 h = __floats2half2_rn(v0, v1);
                *(__half2*)(g_t2h + (size_t)m * 768 + n0 + colL) = h;
            }
        }
    }
}

// ---------------- launch ----------------
extern "C" void kernel_launch(void* const* d_in, const int* in_sizes, int n_in,
                              void* d_out, int out_size) {
    const float* x  = (const float*)d_in[0];
    const float* w1 = (const float*)d_in[1];
    const float* w2 = (const float*)d_in[2];
    const float* wq = (const float*)d_in[3];
    const float* wk = (const float*)d_in[4];
    const float* wv = (const float*)d_in[5];
    float* out = (float*)d_out;

    cudaFuncSetAttribute(gemm_h<0>,  cudaFuncAttributeMaxDynamicSharedMemorySize, SMEMB);
    cudaFuncSetAttribute(gemm_h<2>,  cudaFuncAttributeMaxDynamicSharedMemorySize, SMEMB);
    cudaFuncSetAttribute(gemm_conv,  cudaFuncAttributeMaxDynamicSharedMemorySize, SMEMB);

    kprep_x<<<(40960 * 96 + 255) / 256, 256>>>(x);
    kprep_w<<<(384 * 96 + 255) / 256, 256>>>(w1, 384 * 96, 0);
    kprep_w<<<(768 * 96 + 255) / 256, 256>>>(wq, 768 * 96, 1);
    kprep_w<<<(768 * 96 + 255) / 256, 256>>>(wk, 768 * 96, 2);
    kprep_w<<<(768 * 96 + 255) / 256, 256>>>(wv, 768 * 96, 3);
    kprep_w2t<<<(768 * 3456 + 255) / 256, 256>>>(w2);

    gemm_h<0><<<dim3(3, 320), 256, SMEMB>>>(nullptr);    // t1 = gelu(X@W1^T), [p][b] order
    gemm_conv<<<dim3(6, 320), 256, SMEMB>>>();           // conv3x3, valid taps only
    kfilter<<<(2048 * 192 + 255) / 256, 256>>>();        // gelu + analytic low-pass
    gemm_h<2><<<dim3(18, 64), 256, SMEMB>>>(out);        // QKV + replicated scatter
}

// round 10
// speedup vs baseline: 5.4356x; 1.0193x over previous
#include <cuda_runtime.h>
#include <cuda_fp16.h>
#include <math.h>
#include <stdint.h>

typedef uint32_t u32;
typedef uint64_t u64;

#define OUTSZ (2048u*12u*20u*64u)

// ---------------- static device scratch (fp16, position-major m' = p*2048 + b) ----------------
__device__ __align__(256) __half g_xh  [40960u*768u];   // X reordered [p][b][768]
__device__ __align__(256) __half g_w1h [384u*768u];
__device__ __align__(256) __half g_wqh [768u*768u];
__device__ __align__(256) __half g_wkh [768u*768u];
__device__ __align__(256) __half g_wvh [768u*768u];
__device__ __align__(256) __half g_w2th[768u*3456u];    // w2 -> [o][tap*384+i]
__device__ __align__(256) __half g_t1h [40960u*384u];   // gelu(conv1x1), [p][b][384]
__device__ __align__(256) __half g_t2h [40960u*768u];   // conv3x3 out, [p][b][768]
__device__ __align__(256) __half g_fh  [8192u*768u];    // filtered rows, [b*4+y][768]

// ---------------- helpers ----------------
__device__ __forceinline__ u32 smem_u32(const void* p) {
    u32 a;
    asm("{ .reg .u64 t; cvta.to.shared.u64 t, %1; cvt.u32.u64 %0, t; }" : "=r"(a) : "l"(p));
    return a;
}
__device__ __forceinline__ float gelu_f(float v) {
    return 0.5f * v * (1.0f + erff(v * 0.7071067811865476f));
}

#define CPA(sa, ga, sz) asm volatile("cp.async.cg.shared.global [%0], [%1], 16, %2;" :: "r"(sa), "l"(ga), "r"(sz) : "memory")
#define CPC()  asm volatile("cp.async.commit_group;" ::: "memory")
#define CPW(n) asm volatile("cp.async.wait_group %0;" :: "n"(n) : "memory")

__device__ __forceinline__ void mma16(float* c, const u32* a, const u32* b) {
    asm volatile("mma.sync.aligned.m16n8k16.row.col.f32.f16.f16.f32 "
        "{%0,%1,%2,%3}, {%4,%5,%6,%7}, {%8,%9}, {%0,%1,%2,%3};"
        : "+f"(c[0]), "+f"(c[1]), "+f"(c[2]), "+f"(c[3])
        : "r"(a[0]), "r"(a[1]), "r"(a[2]), "r"(a[3]), "r"(b[0]), "r"(b[1]));
}
__device__ __forceinline__ void ldmx4(u32& r0, u32& r1, u32& r2, u32& r3, u32 addr) {
    asm volatile("ldmatrix.sync.aligned.m8n8.x4.shared.b16 {%0,%1,%2,%3}, [%4];"
                 : "=r"(r0), "=r"(r1), "=r"(r2), "=r"(r3) : "r"(addr));
}
__device__ __forceinline__ uint4 pack8h(float4 a, float4 b) {
    __half2 h0 = __floats2half2_rn(a.x, a.y), h1 = __floats2half2_rn(a.z, a.w);
    __half2 h2 = __floats2half2_rn(b.x, b.y), h3 = __floats2half2_rn(b.z, b.w);
    uint4 u;
    u.x = *(const unsigned*)&h0; u.y = *(const unsigned*)&h1;
    u.z = *(const unsigned*)&h2; u.w = *(const unsigned*)&h3;
    return u;
}

// ---------------- fused prep: X reorder + all weight conversions + w2 transpose ----------------
// region boundaries (FIXED: O1 now includes the w1 granules)
#define XN   3932160            // X: 40960*96 8-float granules          [0, XN)
#define O1   (XN + 36864)       // w1: 36864 granules                    [XN, O1)
#define O2   (O1 + 73728)       // wq: 73728 granules                    [O1, O2)
#define O3   (O2 + 73728)       // wk                                    [O2, O3)
#define O4   (O3 + 73728)       // wv                                    [O3, O4)
#define O5   (O4 + 2654208)     // w2t: 768*3456 single elements         [O4, O5)
#define OT   O5                 // 6844416 total -> 26736 blocks of 256

__global__ void kprep(const float* __restrict__ X,  const float* __restrict__ w1,
                      const float* __restrict__ wq, const float* __restrict__ wk,
                      const float* __restrict__ wv, const float* __restrict__ w2) {
    int idx = blockIdx.x * 256 + threadIdx.x;
    if (idx < XN) {
        int mp = idx / 96, c = idx - mp * 96;
        int p = mp >> 11, b = mp & 2047;
        const float* src = X + ((size_t)b * 21 + 1 + p) * 768 + c * 8;
        float4 a = *(const float4*)src, bb = *(const float4*)(src + 4);
        *(uint4*)(g_xh + (size_t)mp * 768 + c * 8) = pack8h(a, bb);
    } else if (idx < O4) {
        const float* src; __half* dst; int i;
        if (idx < O1)      { i = idx - XN; src = w1; dst = g_w1h; }
        else if (idx < O2) { i = idx - O1; src = wq; dst = g_wqh; }
        else if (idx < O3) { i = idx - O2; src = wk; dst = g_wkh; }
        else               { i = idx - O3; src = wv; dst = g_wvh; }
        float4 a = *(const float4*)(src + (size_t)i * 8);
        float4 b = *(const float4*)(src + (size_t)i * 8 + 4);
        *(uint4*)(dst + (size_t)i * 8) = pack8h(a, b);
    } else if (idx < O5) {
        int i = idx - O4;                 // over 768*3456
        int o = i / 3456, r = i - o * 3456;
        int t = r / 384, ic = r - t * 384;
        g_w2th[i] = __float2half(w2[((size_t)o * 384 + ic) * 9 + t]);
    }
}

// ---------------- filter: gelu + analytic FFT low-pass ----------------
__global__ void kfilter() {
    int idx = blockIdx.x * 256 + threadIdx.x;     // over 2048*192 (4 channels each)
    if (idx >= 2048 * 192) return;
    int b = idx / 192, oq = idx - b * 192;
    const __half* src = g_t2h + (size_t)b * 768 + oq * 4;
    float ry[4][4];
#pragma unroll
    for (int y = 0; y < 4; y++) {
        float a0 = 0.f, a1 = 0.f, a2 = 0.f, a3 = 0.f;
#pragma unroll
        for (int x = 0; x < 5; x++) {
            const __half2* pp = (const __half2*)(src + (size_t)(y * 5 + x) * 2048u * 768u);
            float2 v01 = __half22float2(pp[0]);
            float2 v23 = __half22float2(pp[1]);
            a0 += gelu_f(v01.x); a1 += gelu_f(v01.y);
            a2 += gelu_f(v23.x); a3 += gelu_f(v23.y);
        }
        ry[y][0] = a0; ry[y][1] = a1; ry[y][2] = a2; ry[y][3] = a3;
    }
    __half o[4][4];
#pragma unroll
    for (int j = 0; j < 4; j++) {
        float S  = ry[0][j] + ry[1][j] + ry[2][j] + ry[3][j];
        float A  = ry[0][j] - ry[2][j];
        float Bv = ry[1][j] - ry[3][j];
        o[0][j] = __float2half(sqrtf((S + A) * (S + A) + Bv * Bv) * 0.05f);
        o[1][j] = __float2half(sqrtf((S + Bv) * (S + Bv) + A * A) * 0.05f);
        o[2][j] = __float2half(sqrtf((S - A) * (S - A) + Bv * Bv) * 0.05f);
        o[3][j] = __float2half(sqrtf((S - Bv) * (S - Bv) + A * A) * 0.05f);
    }
    __half* dst = g_fh + (size_t)b * 4 * 768 + oq * 4;
#pragma unroll
    for (int y = 0; y < 4; y++) {
        uint2 u;
        __half2 h0; h0.x = o[y][0]; h0.y = o[y][1];
        __half2 h1; h1.x = o[y][2]; h1.y = o[y][3];
        u.x = *(const unsigned*)&h0; u.y = *(const unsigned*)&h1;
        *(uint2*)(dst + (size_t)y * 768) = u;
    }
}

// =====================================================================
// GEMM geometry: BM=128, BN=128, BK=32, 3-stage cp.async, 8 warps,
// warp tile 64x32, ldmatrix fragments, 2 CTAs/SM, ONE barrier per chunk
// =====================================================================
#define LDSH 40
#define ASMH (128 * LDSH)
#define STGH (2 * ASMH)
#define SMEMB (3 * STGH * 2)

// ---------------- generic GEMM (MODE 0: G1, MODE 2: QKV) ----------------
template<int MODE>
__global__ __launch_bounds__(256, 2) void gemm_h(float* __restrict__ Cout) {
    constexpr int L = 24;                          // 768/32
    extern __shared__ __half smh[];
    const u32 sbase = smem_u32(smh);
    const int tid = threadIdx.x, wid = tid >> 5, lane = tid & 31;
    const int wm = wid >> 2, wn = wid & 3;
    const int lr = lane >> 2, lc = lane & 3;
    const int n0 = blockIdx.x * 128, m0 = blockIdx.y * 128;

    int which = 0, nw0 = n0;
    const __half* Bb;
    if (MODE == 2) {
        which = n0 / 768; nw0 = n0 - which * 768;
        Bb = (which == 0) ? g_wqh : (which == 1) ? g_wkh : g_wvh;
    } else {
        Bb = g_w1h;
    }
    const __half* Ab = (MODE == 0) ? g_xh : g_fh;

    const int arow_t = wm * 64 + ((lane >> 3) & 1) * 8 + (lane & 7);
    const int acol_t = (lane >> 4) * 8;
    const int brow_t = wn * 32 + (lane >> 4) * 8 + (lane & 7);
    const int bcol_t = ((lane >> 3) & 1) * 8;

    u32 saoff[2]; const __half* aptr[2];
    u32 sboff[2]; const __half* bptr[2];
#pragma unroll
    for (int v = 0; v < 2; v++) {
        int idx = v * 256 + tid, r = idx >> 2, c4 = idx & 3;
        saoff[v] = (u32)(r * LDSH + c4 * 8) * 2u;
        aptr[v] = Ab + (size_t)(m0 + r) * 768 + c4 * 8;
        sboff[v] = (u32)(ASMH + r * LDSH + c4 * 8) * 2u;
        bptr[v] = Bb + (size_t)(nw0 + r) * 768 + c4 * 8;
    }

    auto load = [&](int c, int s) {
        u32 base = sbase + (u32)(s * STGH) * 2u;
#pragma unroll
        for (int v = 0; v < 2; v++) CPA(base + saoff[v], aptr[v] + (size_t)c * 32, 16u);
#pragma unroll
        for (int v = 0; v < 2; v++) CPA(base + sboff[v], bptr[v] + (size_t)c * 32, 16u);
        CPC();
    };

    float acc[4][4][4];
#pragma unroll
    for (int i = 0; i < 4; i++)
#pragma unroll
        for (int j = 0; j < 4; j++)
#pragma unroll
            for (int q = 0; q < 4; q++) acc[i][j][q] = 0.f;

    load(0, 0);
    load(1, 1);

    for (int c = 0; c < L; c++) {
        int s = c % 3;
        CPW(1);
        __syncthreads();            // single barrier: all warps done with chunk c-1
        if (c + 2 < L) load(c + 2, (c + 2) % 3); else CPC();

        const u32 sA = sbase + (u32)(s * STGH) * 2u;
        const u32 sB = sA + (u32)ASMH * 2u;
#pragma unroll
        for (int ks = 0; ks < 2; ks++) {
            u32 af[4][4];
#pragma unroll
            for (int mt = 0; mt < 4; mt++) {
                u32 addr = sA + (u32)((arow_t + mt * 16) * LDSH + acol_t + ks * 16) * 2u;
                ldmx4(af[mt][0], af[mt][1], af[mt][2], af[mt][3], addr);
            }
            u32 bf[4][2];
#pragma unroll
            for (int np = 0; np < 2; np++) {
                u32 addr = sB + (u32)((brow_t + np * 16) * LDSH + bcol_t + ks * 16) * 2u;
                ldmx4(bf[np * 2][0], bf[np * 2][1], bf[np * 2 + 1][0], bf[np * 2 + 1][1], addr);
            }
#pragma unroll
            for (int mt = 0; mt < 4; mt++)
#pragma unroll
                for (int nt = 0; nt < 4; nt++)
                    mma16(acc[mt][nt], af[mt], bf[nt]);
        }
    }

#pragma unroll
    for (int mt = 0; mt < 4; mt++) {
        int r0 = m0 + wm * 64 + mt * 16 + lr;
#pragma unroll
        for (int half = 0; half < 2; half++) {
            int m = r0 + half * 8;
#pragma unroll
            for (int nt = 0; nt < 4; nt++) {
                float v0 = acc[mt][nt][half * 2 + 0];
                float v1 = acc[mt][nt][half * 2 + 1];
                int colL = wn * 32 + nt * 8 + lc * 2;
                if (MODE == 0) {
                    __half2 h = __floats2half2_rn(gelu_f(v0), gelu_f(v1));
                    *(__half2*)(g_t1h + (size_t)m * 384 + n0 + colL) = h;
                } else {
                    int b = m >> 2, y = m & 3;
                    int n = nw0 + colL, nh = n >> 6, d = n & 63;
                    float* bp = Cout + (size_t)which * OUTSZ
                              + (((size_t)b * 12 + nh) * 20 + y * 5) * 64 + d;
                    float2 v = make_float2(v0, v1);
#pragma unroll
                    for (int xx = 0; xx < 5; xx++) *(float2*)(bp + xx * 64) = v;
                }
            }
        }
    }
}

// ---------------- conv GEMM: single position per CTA, valid taps, packed tap tables ----------------
__global__ __launch_bounds__(256, 2) void gemm_conv() {
    extern __shared__ __half smh[];
    const u32 sbase = smem_u32(smh);
    const int tid = threadIdx.x, wid = tid >> 5, lane = tid & 31;
    const int wm = wid >> 2, wn = wid & 3;
    const int lr = lane >> 2, lc = lane & 3;
    const int n0 = blockIdx.x * 128, m0 = blockIdx.y * 128;
    const int p = m0 >> 11;
    const int py = p / 5, px = p - py * 5;

    // bit-packed valid-tap tables (no local-memory arrays)
    u64 spack = 0, wpack = 0; int ntap = 0;
#pragma unroll
    for (int dy = -1; dy <= 1; dy++) {
        int ny = py + dy; if ((unsigned)ny >= 4u) continue;
#pragma unroll
        for (int dx = -1; dx <= 1; dx++) {
            int nx = px + dx; if ((unsigned)nx >= 5u) continue;
            spack |= (u64)(ny * 5 + nx) << (5 * ntap);
            wpack |= (u64)((dy + 1) * 3 + (dx + 1)) << (4 * ntap);
            ntap++;
        }
    }
    const int L = ntap * 12;

    const int arow_t = wm * 64 + ((lane >> 3) & 1) * 8 + (lane & 7);
    const int acol_t = (lane >> 4) * 8;
    const int brow_t = wn * 32 + (lane >> 4) * 8 + (lane & 7);
    const int bcol_t = ((lane >> 3) & 1) * 8;

    u32 saoff[2]; size_t aoff[2];
    u32 sboff[2]; const __half* bptr[2];
#pragma unroll
    for (int v = 0; v < 2; v++) {
        int idx = v * 256 + tid, r = idx >> 2, c4 = idx & 3;
        saoff[v] = (u32)(r * LDSH + c4 * 8) * 2u;
        aoff[v] = (size_t)(m0 + r - p * 2048) * 384 + c4 * 8;
        sboff[v] = (u32)(ASMH + r * LDSH + c4 * 8) * 2u;
        bptr[v] = g_w2th + (size_t)(n0 + r) * 3456 + c4 * 8;
    }

    auto load = [&](int c, int s) {
        int ti = c / 12, cc = c - ti * 12, kk = cc * 32;
        int srcp = (int)((spack >> (5 * ti)) & 31u);
        int wt   = (int)((wpack >> (4 * ti)) & 15u);
        const __half* Asl = g_t1h + (size_t)srcp * (2048u * 384u) + kk;
        int boff = wt * 384 + kk;
        u32 base = sbase + (u32)(s * STGH) * 2u;
#pragma unroll
        for (int v = 0; v < 2; v++) CPA(base + saoff[v], Asl + aoff[v], 16u);
#pragma unroll
        for (int v = 0; v < 2; v++) CPA(base + sboff[v], bptr[v] + boff, 16u);
        CPC();
    };

    float acc[4][4][4];
#pragma unroll
    for (int i = 0; i < 4; i++)
#pragma unroll
        for (int j = 0; j < 4; j++)
#pragma unroll
            for (int q = 0; q < 4; q++) acc[i][j][q] = 0.f;

    load(0, 0);
    load(1, 1);

    for (int c = 0; c < L; c++) {
        int s = c % 3;
        CPW(1);
        __syncthreads();            // single barrier per chunk
        if (c + 2 < L) load(c + 2, (c + 2) % 3); else CPC();

        const u32 sA = sbase + (u32)(s * STGH) * 2u;
        const u32 sB = sA + (u32)ASMH * 2u;
#pragma unroll
        for (int ks = 0; ks < 2; ks++) {
            u32 af[4][4];
#pragma unroll
            for (int mt = 0; mt < 4; mt++) {
                u32 addr = sA + (u32)((arow_t + mt * 16) * LDSH + acol_t + ks * 16) * 2u;
                ldmx4(af[mt][0], af[mt][1], af[mt][2], af[mt][3], addr);
            }
            u32 bf[4][2];
#pragma unroll
            for (int np = 0; np < 2; np++) {
                u32 addr = sB + (u32)((brow_t + np * 16) * LDSH + bcol_t + ks * 16) * 2u;
                ldmx4(bf[np * 2][0], bf[np * 2][1], bf[np * 2 + 1][0], bf[np * 2 + 1][1], addr);
            }
#pragma unroll
            for (int mt = 0; mt < 4; mt++)
#pragma unroll
                for (int nt = 0; nt < 4; nt++)
                    mma16(acc[mt][nt], af[mt], bf[nt]);
        }
    }

#pragma unroll
    for (int mt = 0; mt < 4; mt++) {
        int r0 = m0 + wm * 64 + mt * 16 + lr;
#pragma unroll
        for (int half = 0; half < 2; half++) {
            int m = r0 + half * 8;
#pragma unroll
            for (int nt = 0; nt < 4; nt++) {
                float v0 = acc[mt][nt][half * 2 + 0];
                float v1 = acc[mt][nt][half * 2 + 1];
                int colL = wn * 32 + nt * 8 + lc * 2;
                __half2 h = __floats2half2_rn(v0, v1);
                *(__half2*)(g_t2h + (size_t)m * 768 + n0 + colL) = h;
            }
        }
    }
}

// ---------------- launch ----------------
extern "C" void kernel_launch(void* const* d_in, const int* in_sizes, int n_in,
                              void* d_out, int out_size) {
    const float* x  = (const float*)d_in[0];
    const float* w1 = (const float*)d_in[1];
    const float* w2 = (const float*)d_in[2];
    const float* wq = (const float*)d_in[3];
    const float* wk = (const float*)d_in[4];
    const float* wv = (const float*)d_in[5];
    float* out = (float*)d_out;

    cudaFuncSetAttribute(gemm_h<0>, cudaFuncAttributeMaxDynamicSharedMemorySize, SMEMB);
    cudaFuncSetAttribute(gemm_h<2>, cudaFuncAttributeMaxDynamicSharedMemorySize, SMEMB);
    cudaFuncSetAttribute(gemm_conv, cudaFuncAttributeMaxDynamicSharedMemorySize, SMEMB);

    kprep<<<(OT + 255) / 256, 256>>>(x, w1, wq, wk, wv, w2);   // all conversions, one launch
    gemm_h<0><<<dim3(3, 320), 256, SMEMB>>>(nullptr);    // t1 = gelu(X@W1^T), [p][b] order
    gemm_conv<<<dim3(6, 320), 256, SMEMB>>>();           // conv3x3, valid taps only
    kfilter<<<(2048 * 192 + 255) / 256, 256>>>();        // gelu + analytic low-pass
    gemm_h<2><<<dim3(18, 64), 256, SMEMB>>>(out);        // QKV + replicated scatter
}